// round 1
// baseline (speedup 1.0000x reference)
#include <cuda_runtime.h>
#include <cuda_bf16.h>
#include <math.h>

// Problem constants
#define BATCH 2
#define SEQ   2048
#define DMODEL 1024
#define NHEADS 16
#define DHEAD  64
#define MROWS (BATCH*SEQ)            // 4096
#define ATT_OFF ((size_t)BATCH*SEQ*DMODEL)   // 4194304 floats: output region size

// Scratch: g_q, g_k, g_v, g_ctx, g_o : each MROWS*DMODEL floats
__device__ float g_scratch[5ull * MROWS * DMODEL];

// ---------------------------------------------------------------------------
// NT GEMM with bias: C[M,N] = A[M,K] @ W[N,K]^T + bias[N]
// M=4096, N=1024, K=1024. BM=BN=64, BK=16, 256 threads, 4x4 per thread.
// ---------------------------------------------------------------------------
__global__ void gemm_nt_bias(const float* __restrict__ A,
                             const float* __restrict__ W,
                             const float* __restrict__ bias,
                             float* __restrict__ C) {
    __shared__ float As[16][68];
    __shared__ float Bs[16][68];
    const int tid = threadIdx.x;
    const int tx = tid & 15, ty = tid >> 4;
    const int row0 = blockIdx.y * 64;
    const int col0 = blockIdx.x * 64;
    const int Kk = DMODEL, Nn = DMODEL;

    float acc[4][4] = {};
    for (int k0 = 0; k0 < Kk; k0 += 16) {
        #pragma unroll
        for (int i = tid; i < 64 * 16; i += 256) {
            int r = i >> 4, kk = i & 15;
            As[kk][r] = A[(size_t)(row0 + r) * Kk + k0 + kk];
        }
        #pragma unroll
        for (int i = tid; i < 64 * 16; i += 256) {
            int r = i >> 4, kk = i & 15;
            Bs[kk][r] = W[(size_t)(col0 + r) * Kk + k0 + kk];
        }
        __syncthreads();
        #pragma unroll
        for (int kk = 0; kk < 16; kk++) {
            float4 a4 = *reinterpret_cast<const float4*>(&As[kk][ty * 4]);
            float4 b4 = *reinterpret_cast<const float4*>(&Bs[kk][tx * 4]);
            float a[4] = {a4.x, a4.y, a4.z, a4.w};
            float b[4] = {b4.x, b4.y, b4.z, b4.w};
            #pragma unroll
            for (int i = 0; i < 4; i++)
                #pragma unroll
                for (int j = 0; j < 4; j++)
                    acc[i][j] = fmaf(a[i], b[j], acc[i][j]);
        }
        __syncthreads();
    }
    #pragma unroll
    for (int i = 0; i < 4; i++) {
        int r = row0 + ty * 4 + i;
        #pragma unroll
        for (int j = 0; j < 4; j++) {
            int c = col0 + tx * 4 + j;
            C[(size_t)r * Nn + c] = acc[i][j] + bias[c];
        }
    }
}

// ---------------------------------------------------------------------------
// Scores: per (b,h), S = Q @ K^T * (1/8), then mask -> write to attention buf.
// Q,K strided (ld = DMODEL). grid = (S/64, S/64, B*H), 256 threads.
// ---------------------------------------------------------------------------
__global__ void scores_kernel(const float* __restrict__ gq,
                              const float* __restrict__ gk,
                              const int* __restrict__ mask,
                              float* __restrict__ attn) {
    __shared__ float As[16][68];
    __shared__ float Bs[16][68];
    const int tid = threadIdx.x;
    const int tx = tid & 15, ty = tid >> 4;
    const int bh = blockIdx.z;
    const int b = bh / NHEADS, h = bh % NHEADS;
    const float* Q = gq + (size_t)b * SEQ * DMODEL + h * DHEAD;
    const float* Kp = gk + (size_t)b * SEQ * DMODEL + h * DHEAD;
    const int q0 = blockIdx.y * 64;
    const int c0 = blockIdx.x * 64;

    float acc[4][4] = {};
    #pragma unroll
    for (int k0 = 0; k0 < DHEAD; k0 += 16) {
        #pragma unroll
        for (int i = tid; i < 64 * 16; i += 256) {
            int r = i >> 4, kk = i & 15;
            As[kk][r] = Q[(size_t)(q0 + r) * DMODEL + k0 + kk];
        }
        #pragma unroll
        for (int i = tid; i < 64 * 16; i += 256) {
            int r = i >> 4, kk = i & 15;
            Bs[kk][r] = Kp[(size_t)(c0 + r) * DMODEL + k0 + kk];
        }
        __syncthreads();
        #pragma unroll
        for (int kk = 0; kk < 16; kk++) {
            float4 a4 = *reinterpret_cast<const float4*>(&As[kk][ty * 4]);
            float4 b4 = *reinterpret_cast<const float4*>(&Bs[kk][tx * 4]);
            float a[4] = {a4.x, a4.y, a4.z, a4.w};
            float b[4] = {b4.x, b4.y, b4.z, b4.w};
            #pragma unroll
            for (int i = 0; i < 4; i++)
                #pragma unroll
                for (int j = 0; j < 4; j++)
                    acc[i][j] = fmaf(a[i], b[j], acc[i][j]);
        }
        __syncthreads();
    }
    const int* mrow = mask + (size_t)b * SEQ * SEQ;
    float* out = attn + (size_t)bh * SEQ * SEQ;
    #pragma unroll
    for (int i = 0; i < 4; i++) {
        int qq = q0 + ty * 4 + i;
        #pragma unroll
        for (int j = 0; j < 4; j++) {
            int kk2 = c0 + tx * 4 + j;
            float v = acc[i][j] * 0.125f;
            if (mrow[(size_t)qq * SEQ + kk2] == 0) v = -1000000000.0f;
            out[(size_t)qq * SEQ + kk2] = v;
        }
    }
}

// ---------------------------------------------------------------------------
// Row softmax in place over attention buffer. One block per row (B*H*S rows).
// 256 threads, 8 elements per thread (S=2048).
// ---------------------------------------------------------------------------
__global__ void softmax_kernel(float* __restrict__ attn) {
    const size_t row = blockIdx.x;
    float* p = attn + row * (size_t)SEQ;
    const int t = threadIdx.x;
    __shared__ float smax[8];
    __shared__ float ssum[8];

    float v[8];
    float mx = -3.4e38f;
    #pragma unroll
    for (int i = 0; i < 8; i++) {
        v[i] = p[t + i * 256];
        mx = fmaxf(mx, v[i]);
    }
    #pragma unroll
    for (int o = 16; o > 0; o >>= 1)
        mx = fmaxf(mx, __shfl_xor_sync(0xffffffffu, mx, o));
    if ((t & 31) == 0) smax[t >> 5] = mx;
    __syncthreads();
    float m = smax[0];
    #pragma unroll
    for (int i = 1; i < 8; i++) m = fmaxf(m, smax[i]);

    float s = 0.f;
    #pragma unroll
    for (int i = 0; i < 8; i++) {
        v[i] = __expf(v[i] - m);
        s += v[i];
    }
    #pragma unroll
    for (int o = 16; o > 0; o >>= 1)
        s += __shfl_xor_sync(0xffffffffu, s, o);
    if ((t & 31) == 0) ssum[t >> 5] = s;
    __syncthreads();
    float tot = 0.f;
    #pragma unroll
    for (int i = 0; i < 8; i++) tot += ssum[i];
    float inv = 1.0f / tot;
    #pragma unroll
    for (int i = 0; i < 8; i++)
        p[t + i * 256] = v[i] * inv;
}

// ---------------------------------------------------------------------------
// PV: per (b,h), ctx[S,64] = P[S,S] @ V[S,64] (V strided, ld=DMODEL).
// grid = (1, S/64, B*H). BM=64, BN=64(=DHEAD), BK=16, 256 threads, 4x4.
// ---------------------------------------------------------------------------
__global__ void pv_kernel(const float* __restrict__ attn,
                          const float* __restrict__ gv,
                          float* __restrict__ gctx) {
    __shared__ float As[16][68];
    __shared__ float Bs[16][68];
    const int tid = threadIdx.x;
    const int tx = tid & 15, ty = tid >> 4;
    const int bh = blockIdx.z;
    const int b = bh / NHEADS, h = bh % NHEADS;
    const float* P = attn + (size_t)bh * SEQ * SEQ;
    const float* V = gv + (size_t)b * SEQ * DMODEL + h * DHEAD;
    float* Cc = gctx + (size_t)b * SEQ * DMODEL + h * DHEAD;
    const int q0 = blockIdx.y * 64;

    float acc[4][4] = {};
    for (int k0 = 0; k0 < SEQ; k0 += 16) {
        #pragma unroll
        for (int i = tid; i < 64 * 16; i += 256) {
            int r = i >> 4, kk = i & 15;
            As[kk][r] = P[(size_t)(q0 + r) * SEQ + k0 + kk];
        }
        #pragma unroll
        for (int i = tid; i < 16 * 64; i += 256) {
            int kk = i >> 6, c = i & 63;
            Bs[kk][c] = V[(size_t)(k0 + kk) * DMODEL + c];
        }
        __syncthreads();
        #pragma unroll
        for (int kk = 0; kk < 16; kk++) {
            float4 a4 = *reinterpret_cast<const float4*>(&As[kk][ty * 4]);
            float4 b4 = *reinterpret_cast<const float4*>(&Bs[kk][tx * 4]);
            float a[4] = {a4.x, a4.y, a4.z, a4.w};
            float b[4] = {b4.x, b4.y, b4.z, b4.w};
            #pragma unroll
            for (int i = 0; i < 4; i++)
                #pragma unroll
                for (int j = 0; j < 4; j++)
                    acc[i][j] = fmaf(a[i], b[j], acc[i][j]);
        }
        __syncthreads();
    }
    #pragma unroll
    for (int i = 0; i < 4; i++) {
        int r = q0 + ty * 4 + i;
        #pragma unroll
        for (int j = 0; j < 4; j++) {
            int c = tx * 4 + j;
            Cc[(size_t)r * DMODEL + c] = acc[i][j];
        }
    }
}

// ---------------------------------------------------------------------------
// Residual + LayerNorm: out[row,:] = LN(resid[row,:] + x[row,:]) * gamma + beta
// One block per row (4096). 256 threads, 4 elements each (D=1024).
// ---------------------------------------------------------------------------
__global__ void ln_kernel(const float* __restrict__ resid,
                          const float* __restrict__ x,
                          const float* __restrict__ gamma,
                          const float* __restrict__ beta,
                          float* __restrict__ out) {
    const size_t row = blockIdx.x;
    const float* xr = x + row * DMODEL;
    const float* rr = resid + row * DMODEL;
    const int t = threadIdx.x;
    __shared__ float s1[8];
    __shared__ float s2[8];

    float v[4];
    float s = 0.f;
    #pragma unroll
    for (int i = 0; i < 4; i++) {
        v[i] = rr[t + i * 256] + xr[t + i * 256];
        s += v[i];
    }
    #pragma unroll
    for (int o = 16; o > 0; o >>= 1) s += __shfl_xor_sync(0xffffffffu, s, o);
    if ((t & 31) == 0) s1[t >> 5] = s;
    __syncthreads();
    float tot = 0.f;
    #pragma unroll
    for (int i = 0; i < 8; i++) tot += s1[i];
    const float mu = tot * (1.0f / DMODEL);

    float sq = 0.f;
    #pragma unroll
    for (int i = 0; i < 4; i++) {
        float d = v[i] - mu;
        sq += d * d;
    }
    #pragma unroll
    for (int o = 16; o > 0; o >>= 1) sq += __shfl_xor_sync(0xffffffffu, sq, o);
    if ((t & 31) == 0) s2[t >> 5] = sq;
    __syncthreads();
    float tot2 = 0.f;
    #pragma unroll
    for (int i = 0; i < 8; i++) tot2 += s2[i];
    const float var = tot2 * (1.0f / DMODEL);
    const float inv = rsqrtf(var + 1e-5f);

    #pragma unroll
    for (int i = 0; i < 4; i++) {
        int c = t + i * 256;
        out[row * DMODEL + c] = (v[i] - mu) * inv * gamma[c] + beta[c];
    }
}

// ---------------------------------------------------------------------------
extern "C" void kernel_launch(void* const* d_in, const int* in_sizes, int n_in,
                              void* d_out, int out_size) {
    const float* q     = (const float*)d_in[0];
    const float* k     = (const float*)d_in[1];
    const float* v     = (const float*)d_in[2];
    const int*   mask  = (const int*)  d_in[3];
    const float* wq    = (const float*)d_in[4];
    const float* bq    = (const float*)d_in[5];
    const float* wk    = (const float*)d_in[6];
    const float* bk    = (const float*)d_in[7];
    const float* wv    = (const float*)d_in[8];
    const float* bv    = (const float*)d_in[9];
    const float* wo    = (const float*)d_in[10];
    const float* bo    = (const float*)d_in[11];
    const float* gamma = (const float*)d_in[12];
    const float* beta  = (const float*)d_in[13];

    float* out  = (float*)d_out;
    float* attn = out + ATT_OFF;

    void* sp = nullptr;
    cudaGetSymbolAddress(&sp, g_scratch);
    float* gq   = (float*)sp;
    float* gk   = gq   + (size_t)MROWS * DMODEL;
    float* gv   = gk   + (size_t)MROWS * DMODEL;
    float* gctx = gv   + (size_t)MROWS * DMODEL;
    float* go   = gctx + (size_t)MROWS * DMODEL;

    dim3 gProj(DMODEL / 64, MROWS / 64);               // (16, 64)
    gemm_nt_bias<<<gProj, 256>>>(q, wq, bq, gq);
    gemm_nt_bias<<<gProj, 256>>>(k, wk, bk, gk);
    gemm_nt_bias<<<gProj, 256>>>(v, wv, bv, gv);

    dim3 gScores(SEQ / 64, SEQ / 64, BATCH * NHEADS);  // (32, 32, 32)
    scores_kernel<<<gScores, 256>>>(gq, gk, mask, attn);

    softmax_kernel<<<BATCH * NHEADS * SEQ, 256>>>(attn);

    dim3 gPV(1, SEQ / 64, BATCH * NHEADS);             // (1, 32, 32)
    pv_kernel<<<gPV, 256>>>(attn, gv, gctx);

    gemm_nt_bias<<<gProj, 256>>>(gctx, wo, bo, go);

    ln_kernel<<<MROWS, 256>>>(q, go, gamma, beta, out);
}

// round 2
// speedup vs baseline: 1.4582x; 1.4582x over previous
#include <cuda_runtime.h>
#include <cuda_bf16.h>
#include <math.h>

#define BATCH 2
#define SEQ   2048
#define DMODEL 1024
#define NHEADS 16
#define DHEAD  64
#define MROWS (BATCH*SEQ)                    // 4096
#define ATT_OFF ((size_t)BATCH*SEQ*DMODEL)   // output region floats

__device__ float g_scratch[5ull * MROWS * DMODEL];

// ---------------------------------------------------------------------------
// NT GEMM + bias: C[M,N] = A[M,K] @ W[N,K]^T + bias
// M=4096, N=1024, K=1024. BM=BN=128, BK=8, 256 threads, 8x8 per thread.
// ---------------------------------------------------------------------------
__global__ __launch_bounds__(256, 2)
void gemm_nt_bias(const float* __restrict__ A,
                  const float* __restrict__ W,
                  const float* __restrict__ bias,
                  float* __restrict__ C) {
    __shared__ float As[8][132];
    __shared__ float Bs[8][132];
    const int tid = threadIdx.x;
    const int lr = tid >> 1;              // 0..127
    const int lk = (tid & 1) << 2;        // 0 or 4
    const int ty = tid >> 4;              // 0..15 (row group)
    const int tx = tid & 15;              // 0..15 (col group)
    const int row0 = blockIdx.y * 128;
    const int col0 = blockIdx.x * 128;

    float acc[8][8] = {};
    const float* Ap = A + (size_t)(row0 + lr) * DMODEL + lk;
    const float* Wp = W + (size_t)(col0 + lr) * DMODEL + lk;

    for (int k0 = 0; k0 < DMODEL; k0 += 8) {
        float4 a4 = *reinterpret_cast<const float4*>(Ap + k0);
        float4 b4 = *reinterpret_cast<const float4*>(Wp + k0);
        As[lk + 0][lr] = a4.x; As[lk + 1][lr] = a4.y;
        As[lk + 2][lr] = a4.z; As[lk + 3][lr] = a4.w;
        Bs[lk + 0][lr] = b4.x; Bs[lk + 1][lr] = b4.y;
        Bs[lk + 2][lr] = b4.z; Bs[lk + 3][lr] = b4.w;
        __syncthreads();
        #pragma unroll
        for (int kk = 0; kk < 8; kk++) {
            float4 a0 = *reinterpret_cast<const float4*>(&As[kk][ty * 8]);
            float4 a1 = *reinterpret_cast<const float4*>(&As[kk][ty * 8 + 4]);
            float4 b0 = *reinterpret_cast<const float4*>(&Bs[kk][tx * 8]);
            float4 b1 = *reinterpret_cast<const float4*>(&Bs[kk][tx * 8 + 4]);
            float a[8] = {a0.x,a0.y,a0.z,a0.w,a1.x,a1.y,a1.z,a1.w};
            float b[8] = {b0.x,b0.y,b0.z,b0.w,b1.x,b1.y,b1.z,b1.w};
            #pragma unroll
            for (int i = 0; i < 8; i++)
                #pragma unroll
                for (int j = 0; j < 8; j++)
                    acc[i][j] = fmaf(a[i], b[j], acc[i][j]);
        }
        __syncthreads();
    }
    float4 bia0 = *reinterpret_cast<const float4*>(&bias[col0 + tx * 8]);
    float4 bia1 = *reinterpret_cast<const float4*>(&bias[col0 + tx * 8 + 4]);
    #pragma unroll
    for (int i = 0; i < 8; i++) {
        size_t r = row0 + ty * 8 + i;
        float4 o0 = {acc[i][0]+bia0.x, acc[i][1]+bia0.y, acc[i][2]+bia0.z, acc[i][3]+bia0.w};
        float4 o1 = {acc[i][4]+bia1.x, acc[i][5]+bia1.y, acc[i][6]+bia1.z, acc[i][7]+bia1.w};
        *reinterpret_cast<float4*>(&C[r * DMODEL + col0 + tx * 8])     = o0;
        *reinterpret_cast<float4*>(&C[r * DMODEL + col0 + tx * 8 + 4]) = o1;
    }
}

// ---------------------------------------------------------------------------
// Scores: per (b,h), S = Q@K^T * 0.125, masked -> attn. 128x128 tile, K=64.
// ---------------------------------------------------------------------------
__global__ __launch_bounds__(256, 2)
void scores_kernel(const float* __restrict__ gq,
                   const float* __restrict__ gk,
                   const int* __restrict__ mask,
                   float* __restrict__ attn) {
    __shared__ float As[8][132];
    __shared__ float Bs[8][132];
    const int tid = threadIdx.x;
    const int lr = tid >> 1;
    const int lk = (tid & 1) << 2;
    const int ty = tid >> 4;
    const int tx = tid & 15;
    const int bh = blockIdx.z;
    const int b = bh >> 4, h = bh & 15;
    const int q0 = blockIdx.y * 128;
    const int c0 = blockIdx.x * 128;
    const float* Qp = gq + (size_t)b * SEQ * DMODEL + (size_t)(q0 + lr) * DMODEL + h * DHEAD + lk;
    const float* Kp = gk + (size_t)b * SEQ * DMODEL + (size_t)(c0 + lr) * DMODEL + h * DHEAD + lk;

    float acc[8][8] = {};
    #pragma unroll
    for (int k0 = 0; k0 < DHEAD; k0 += 8) {
        float4 a4 = *reinterpret_cast<const float4*>(Qp + k0);
        float4 b4 = *reinterpret_cast<const float4*>(Kp + k0);
        As[lk + 0][lr] = a4.x; As[lk + 1][lr] = a4.y;
        As[lk + 2][lr] = a4.z; As[lk + 3][lr] = a4.w;
        Bs[lk + 0][lr] = b4.x; Bs[lk + 1][lr] = b4.y;
        Bs[lk + 2][lr] = b4.z; Bs[lk + 3][lr] = b4.w;
        __syncthreads();
        #pragma unroll
        for (int kk = 0; kk < 8; kk++) {
            float4 a0 = *reinterpret_cast<const float4*>(&As[kk][ty * 8]);
            float4 a1 = *reinterpret_cast<const float4*>(&As[kk][ty * 8 + 4]);
            float4 b0 = *reinterpret_cast<const float4*>(&Bs[kk][tx * 8]);
            float4 b1 = *reinterpret_cast<const float4*>(&Bs[kk][tx * 8 + 4]);
            float a[8] = {a0.x,a0.y,a0.z,a0.w,a1.x,a1.y,a1.z,a1.w};
            float bb[8] = {b0.x,b0.y,b0.z,b0.w,b1.x,b1.y,b1.z,b1.w};
            #pragma unroll
            for (int i = 0; i < 8; i++)
                #pragma unroll
                for (int j = 0; j < 8; j++)
                    acc[i][j] = fmaf(a[i], bb[j], acc[i][j]);
        }
        __syncthreads();
    }
    const int* mrow = mask + (size_t)b * SEQ * SEQ;
    float* out = attn + (size_t)bh * SEQ * SEQ;
    #pragma unroll
    for (int i = 0; i < 8; i++) {
        size_t qq = q0 + ty * 8 + i;
        int4 m0 = *reinterpret_cast<const int4*>(&mrow[qq * SEQ + c0 + tx * 8]);
        int4 m1 = *reinterpret_cast<const int4*>(&mrow[qq * SEQ + c0 + tx * 8 + 4]);
        float4 o0, o1;
        o0.x = m0.x ? acc[i][0]*0.125f : -1e9f;
        o0.y = m0.y ? acc[i][1]*0.125f : -1e9f;
        o0.z = m0.z ? acc[i][2]*0.125f : -1e9f;
        o0.w = m0.w ? acc[i][3]*0.125f : -1e9f;
        o1.x = m1.x ? acc[i][4]*0.125f : -1e9f;
        o1.y = m1.y ? acc[i][5]*0.125f : -1e9f;
        o1.z = m1.z ? acc[i][6]*0.125f : -1e9f;
        o1.w = m1.w ? acc[i][7]*0.125f : -1e9f;
        *reinterpret_cast<float4*>(&out[qq * SEQ + c0 + tx * 8])     = o0;
        *reinterpret_cast<float4*>(&out[qq * SEQ + c0 + tx * 8 + 4]) = o1;
    }
}

// ---------------------------------------------------------------------------
// Row softmax in place. One block per row, 256 threads, float4.
// ---------------------------------------------------------------------------
__global__ void softmax_kernel(float* __restrict__ attn) {
    float4* p = reinterpret_cast<float4*>(attn + blockIdx.x * (size_t)SEQ);
    const int t = threadIdx.x;
    __shared__ float sred[8];

    float4 v0 = p[t], v1 = p[t + 256];
    float mx = fmaxf(fmaxf(fmaxf(v0.x, v0.y), fmaxf(v0.z, v0.w)),
                     fmaxf(fmaxf(v1.x, v1.y), fmaxf(v1.z, v1.w)));
    #pragma unroll
    for (int o = 16; o > 0; o >>= 1)
        mx = fmaxf(mx, __shfl_xor_sync(0xffffffffu, mx, o));
    if ((t & 31) == 0) sred[t >> 5] = mx;
    __syncthreads();
    float m = sred[0];
    #pragma unroll
    for (int i = 1; i < 8; i++) m = fmaxf(m, sred[i]);
    __syncthreads();

    v0.x = __expf(v0.x - m); v0.y = __expf(v0.y - m);
    v0.z = __expf(v0.z - m); v0.w = __expf(v0.w - m);
    v1.x = __expf(v1.x - m); v1.y = __expf(v1.y - m);
    v1.z = __expf(v1.z - m); v1.w = __expf(v1.w - m);
    float s = v0.x + v0.y + v0.z + v0.w + v1.x + v1.y + v1.z + v1.w;
    #pragma unroll
    for (int o = 16; o > 0; o >>= 1)
        s += __shfl_xor_sync(0xffffffffu, s, o);
    if ((t & 31) == 0) sred[t >> 5] = s;
    __syncthreads();
    float tot = 0.f;
    #pragma unroll
    for (int i = 0; i < 8; i++) tot += sred[i];
    float inv = 1.0f / tot;
    v0.x *= inv; v0.y *= inv; v0.z *= inv; v0.w *= inv;
    v1.x *= inv; v1.y *= inv; v1.z *= inv; v1.w *= inv;
    p[t] = v0; p[t + 256] = v1;
}

// ---------------------------------------------------------------------------
// PV: ctx[S,64] = P[S,S] @ V[S,64]. BM=128, BN=64, BK=16, 8x4 per thread.
// ---------------------------------------------------------------------------
__global__ __launch_bounds__(256, 2)
void pv_kernel(const float* __restrict__ attn,
               const float* __restrict__ gv,
               float* __restrict__ gctx) {
    __shared__ float Ps[16][132];
    __shared__ float Vs[16][68];
    const int tid = threadIdx.x;
    const int ty = tid >> 4;
    const int tx = tid & 15;
    const int bh = blockIdx.z;
    const int b = bh >> 4, h = bh & 15;
    const float* P = attn + (size_t)bh * SEQ * SEQ;
    const float* V = gv + (size_t)b * SEQ * DMODEL + h * DHEAD;
    float* Cc = gctx + (size_t)b * SEQ * DMODEL + h * DHEAD;
    const int q0 = blockIdx.y * 128;

    float acc[8][4] = {};
    for (int k0 = 0; k0 < SEQ; k0 += 16) {
        #pragma unroll
        for (int l = 0; l < 2; l++) {
            int idx = tid + l * 256;              // float4 index, 512 total
            int r = idx >> 2;                     // 0..127
            int kc = (idx & 3) << 2;              // 0,4,8,12
            float4 a4 = *reinterpret_cast<const float4*>(
                &P[(size_t)(q0 + r) * SEQ + k0 + kc]);
            Ps[kc + 0][r] = a4.x; Ps[kc + 1][r] = a4.y;
            Ps[kc + 2][r] = a4.z; Ps[kc + 3][r] = a4.w;
        }
        {
            int kk = tid >> 4;                    // 0..15
            int c = (tid & 15) << 2;              // 0..60
            float4 b4 = *reinterpret_cast<const float4*>(
                &V[(size_t)(k0 + kk) * DMODEL + c]);
            *reinterpret_cast<float4*>(&Vs[kk][c]) = b4;
        }
        __syncthreads();
        #pragma unroll
        for (int kk = 0; kk < 16; kk++) {
            float4 a0 = *reinterpret_cast<const float4*>(&Ps[kk][ty * 8]);
            float4 a1 = *reinterpret_cast<const float4*>(&Ps[kk][ty * 8 + 4]);
            float4 b0 = *reinterpret_cast<const float4*>(&Vs[kk][tx * 4]);
            float a[8] = {a0.x,a0.y,a0.z,a0.w,a1.x,a1.y,a1.z,a1.w};
            float bb[4] = {b0.x,b0.y,b0.z,b0.w};
            #pragma unroll
            for (int i = 0; i < 8; i++)
                #pragma unroll
                for (int j = 0; j < 4; j++)
                    acc[i][j] = fmaf(a[i], bb[j], acc[i][j]);
        }
        __syncthreads();
    }
    #pragma unroll
    for (int i = 0; i < 8; i++) {
        size_t r = q0 + ty * 8 + i;
        float4 o = {acc[i][0], acc[i][1], acc[i][2], acc[i][3]};
        *reinterpret_cast<float4*>(&Cc[r * DMODEL + tx * 4]) = o;
    }
}

// ---------------------------------------------------------------------------
// Residual + LayerNorm. One block per row, 256 threads, float4.
// ---------------------------------------------------------------------------
__global__ void ln_kernel(const float* __restrict__ resid,
                          const float* __restrict__ x,
                          const float* __restrict__ gamma,
                          const float* __restrict__ beta,
                          float* __restrict__ out) {
    const size_t row = blockIdx.x;
    const float4* xr = reinterpret_cast<const float4*>(x + row * DMODEL);
    const float4* rr = reinterpret_cast<const float4*>(resid + row * DMODEL);
    const int t = threadIdx.x;
    __shared__ float sred[8];

    float4 a = rr[t], bv = xr[t];
    float4 v = {a.x + bv.x, a.y + bv.y, a.z + bv.z, a.w + bv.w};
    float s = v.x + v.y + v.z + v.w;
    #pragma unroll
    for (int o = 16; o > 0; o >>= 1) s += __shfl_xor_sync(0xffffffffu, s, o);
    if ((t & 31) == 0) sred[t >> 5] = s;
    __syncthreads();
    float tot = 0.f;
    #pragma unroll
    for (int i = 0; i < 8; i++) tot += sred[i];
    const float mu = tot * (1.0f / DMODEL);
    __syncthreads();

    float dx = v.x - mu, dy = v.y - mu, dz = v.z - mu, dw = v.w - mu;
    float sq = dx*dx + dy*dy + dz*dz + dw*dw;
    #pragma unroll
    for (int o = 16; o > 0; o >>= 1) sq += __shfl_xor_sync(0xffffffffu, sq, o);
    if ((t & 31) == 0) sred[t >> 5] = sq;
    __syncthreads();
    float tot2 = 0.f;
    #pragma unroll
    for (int i = 0; i < 8; i++) tot2 += sred[i];
    const float inv = rsqrtf(tot2 * (1.0f / DMODEL) + 1e-5f);

    float4 g = reinterpret_cast<const float4*>(gamma)[t];
    float4 be = reinterpret_cast<const float4*>(beta)[t];
    float4 o;
    o.x = dx * inv * g.x + be.x;
    o.y = dy * inv * g.y + be.y;
    o.z = dz * inv * g.z + be.z;
    o.w = dw * inv * g.w + be.w;
    reinterpret_cast<float4*>(out + row * DMODEL)[t] = o;
}

// ---------------------------------------------------------------------------
extern "C" void kernel_launch(void* const* d_in, const int* in_sizes, int n_in,
                              void* d_out, int out_size) {
    const float* q     = (const float*)d_in[0];
    const float* k     = (const float*)d_in[1];
    const float* v     = (const float*)d_in[2];
    const int*   mask  = (const int*)  d_in[3];
    const float* wq    = (const float*)d_in[4];
    const float* bq    = (const float*)d_in[5];
    const float* wk    = (const float*)d_in[6];
    const float* bk    = (const float*)d_in[7];
    const float* wv    = (const float*)d_in[8];
    const float* bv    = (const float*)d_in[9];
    const float* wo    = (const float*)d_in[10];
    const float* bo    = (const float*)d_in[11];
    const float* gamma = (const float*)d_in[12];
    const float* beta  = (const float*)d_in[13];

    float* out  = (float*)d_out;
    float* attn = out + ATT_OFF;

    void* sp = nullptr;
    cudaGetSymbolAddress(&sp, g_scratch);
    float* gq   = (float*)sp;
    float* gk   = gq   + (size_t)MROWS * DMODEL;
    float* gv   = gk   + (size_t)MROWS * DMODEL;
    float* gctx = gv   + (size_t)MROWS * DMODEL;
    float* go   = gctx + (size_t)MROWS * DMODEL;

    dim3 gProj(DMODEL / 128, MROWS / 128);              // (8, 32)
    gemm_nt_bias<<<gProj, 256>>>(q, wq, bq, gq);
    gemm_nt_bias<<<gProj, 256>>>(k, wk, bk, gk);
    gemm_nt_bias<<<gProj, 256>>>(v, wv, bv, gv);

    dim3 gScores(SEQ / 128, SEQ / 128, BATCH * NHEADS); // (16, 16, 32)
    scores_kernel<<<gScores, 256>>>(gq, gk, mask, attn);

    softmax_kernel<<<BATCH * NHEADS * SEQ, 256>>>(attn);

    dim3 gPV(1, SEQ / 128, BATCH * NHEADS);             // (1, 16, 32)
    pv_kernel<<<gPV, 256>>>(attn, gv, gctx);

    gemm_nt_bias<<<gProj, 256>>>(gctx, wo, bo, go);

    ln_kernel<<<MROWS, 256>>>(q, go, gamma, beta, out);
}

// round 3
// speedup vs baseline: 1.9508x; 1.3378x over previous
#include <cuda_runtime.h>
#include <cuda_bf16.h>
#include <math.h>

#define BATCH 2
#define SEQ   2048
#define DMODEL 1024
#define NHEADS 16
#define DHEAD  64
#define MROWS (BATCH*SEQ)                    // 4096
#define ATT_OFF ((size_t)BATCH*SEQ*DMODEL)

__device__ float g_scratch[5ull * MROWS * DMODEL];

// ---------------------------------------------------------------------------
__device__ __forceinline__ unsigned f2tf(float x) {
    unsigned r;
    asm("cvt.rna.tf32.f32 %0, %1;" : "=r"(r) : "f"(x));
    return r;
}
__device__ __forceinline__ void split2(float x, unsigned& hi, unsigned& lo) {
    hi = f2tf(x);
    lo = f2tf(x - __uint_as_float(hi));
}
__device__ __forceinline__ void mma8(float* d, const unsigned* a, const unsigned* b) {
    asm volatile(
        "mma.sync.aligned.m16n8k8.row.col.f32.tf32.tf32.f32 "
        "{%0,%1,%2,%3}, {%4,%5,%6,%7}, {%8,%9}, {%0,%1,%2,%3};"
        : "+f"(d[0]), "+f"(d[1]), "+f"(d[2]), "+f"(d[3])
        : "r"(a[0]), "r"(a[1]), "r"(a[2]), "r"(a[3]), "r"(b[0]), "r"(b[1]));
}

// ---------------------------------------------------------------------------
// 1x TF32 NT GEMM + bias: C[M,N] = A[M,K] @ W[N,K]^T + bias
// block 128x128, BK=16, 256 thr, warps 4(M)x2(N), warp tile 32x64.
// ---------------------------------------------------------------------------
__global__ __launch_bounds__(256, 2)
void gemm_nt_tf32(const float* __restrict__ A, const float* __restrict__ W,
                  const float* __restrict__ bias, float* __restrict__ C) {
    __shared__ unsigned As[16][136];
    __shared__ unsigned Bs[16][136];
    const int tid = threadIdx.x, lane = tid & 31, warp = tid >> 5;
    const int wm = (warp & 3) * 32, wn = (warp >> 2) * 64;
    const int row0 = blockIdx.y * 128, col0 = blockIdx.x * 128;

    float acc[2][8][4] = {};
    for (int k0 = 0; k0 < DMODEL; k0 += 16) {
        #pragma unroll
        for (int l = 0; l < 2; l++) {
            int idx = tid + l * 256, r = idx >> 2, kc = (idx & 3) << 2;
            float4 a4 = *(const float4*)&A[(size_t)(row0 + r) * DMODEL + k0 + kc];
            float4 b4 = *(const float4*)&W[(size_t)(col0 + r) * DMODEL + k0 + kc];
            As[kc+0][r]=f2tf(a4.x); As[kc+1][r]=f2tf(a4.y); As[kc+2][r]=f2tf(a4.z); As[kc+3][r]=f2tf(a4.w);
            Bs[kc+0][r]=f2tf(b4.x); Bs[kc+1][r]=f2tf(b4.y); Bs[kc+2][r]=f2tf(b4.z); Bs[kc+3][r]=f2tf(b4.w);
        }
        __syncthreads();
        #pragma unroll
        for (int kk = 0; kk < 16; kk += 8) {
            const int kr = kk + (lane & 3), m0 = wm + (lane >> 2);
            unsigned af[2][4];
            #pragma unroll
            for (int i = 0; i < 2; i++) {
                af[i][0] = As[kr][m0 + i*16];     af[i][1] = As[kr][m0 + i*16 + 8];
                af[i][2] = As[kr+4][m0 + i*16];   af[i][3] = As[kr+4][m0 + i*16 + 8];
            }
            #pragma unroll
            for (int j = 0; j < 8; j++) {
                int nb = wn + j * 8 + (lane >> 2);
                unsigned bf[2] = {Bs[kr][nb], Bs[kr+4][nb]};
                mma8(acc[0][j], af[0], bf);
                mma8(acc[1][j], af[1], bf);
            }
        }
        __syncthreads();
    }
    #pragma unroll
    for (int j = 0; j < 8; j++) {
        int c = col0 + wn + j * 8 + (lane & 3) * 2;
        float2 bb = *(const float2*)&bias[c];
        #pragma unroll
        for (int i = 0; i < 2; i++) {
            size_t r = row0 + wm + i * 16 + (lane >> 2);
            float2 o0 = {acc[i][j][0] + bb.x, acc[i][j][1] + bb.y};
            float2 o1 = {acc[i][j][2] + bb.x, acc[i][j][3] + bb.y};
            *(float2*)&C[r * DMODEL + c]       = o0;
            *(float2*)&C[(r + 8) * DMODEL + c] = o1;
        }
    }
}

// ---------------------------------------------------------------------------
// 3xTF32 (split) NT GEMM + bias — high precision path for q/k projections.
// ---------------------------------------------------------------------------
__global__ __launch_bounds__(256, 2)
void gemm_nt_tf32x3(const float* __restrict__ A, const float* __restrict__ W,
                    const float* __restrict__ bias, float* __restrict__ C) {
    __shared__ unsigned Ah[16][136], Al[16][136];
    __shared__ unsigned Bh[16][136], Bl[16][136];
    const int tid = threadIdx.x, lane = tid & 31, warp = tid >> 5;
    const int wm = (warp & 3) * 32, wn = (warp >> 2) * 64;
    const int row0 = blockIdx.y * 128, col0 = blockIdx.x * 128;

    float acc[2][8][4] = {};
    for (int k0 = 0; k0 < DMODEL; k0 += 16) {
        #pragma unroll
        for (int l = 0; l < 2; l++) {
            int idx = tid + l * 256, r = idx >> 2, kc = (idx & 3) << 2;
            float4 a4 = *(const float4*)&A[(size_t)(row0 + r) * DMODEL + k0 + kc];
            float4 b4 = *(const float4*)&W[(size_t)(col0 + r) * DMODEL + k0 + kc];
            split2(a4.x, Ah[kc+0][r], Al[kc+0][r]); split2(a4.y, Ah[kc+1][r], Al[kc+1][r]);
            split2(a4.z, Ah[kc+2][r], Al[kc+2][r]); split2(a4.w, Ah[kc+3][r], Al[kc+3][r]);
            split2(b4.x, Bh[kc+0][r], Bl[kc+0][r]); split2(b4.y, Bh[kc+1][r], Bl[kc+1][r]);
            split2(b4.z, Bh[kc+2][r], Bl[kc+2][r]); split2(b4.w, Bh[kc+3][r], Bl[kc+3][r]);
        }
        __syncthreads();
        #pragma unroll
        for (int kk = 0; kk < 16; kk += 8) {
            const int kr = kk + (lane & 3), m0 = wm + (lane >> 2);
            unsigned ah[2][4], al[2][4];
            #pragma unroll
            for (int i = 0; i < 2; i++) {
                ah[i][0]=Ah[kr][m0+i*16];   ah[i][1]=Ah[kr][m0+i*16+8];
                ah[i][2]=Ah[kr+4][m0+i*16]; ah[i][3]=Ah[kr+4][m0+i*16+8];
                al[i][0]=Al[kr][m0+i*16];   al[i][1]=Al[kr][m0+i*16+8];
                al[i][2]=Al[kr+4][m0+i*16]; al[i][3]=Al[kr+4][m0+i*16+8];
            }
            #pragma unroll
            for (int j = 0; j < 8; j++) {
                int nb = wn + j * 8 + (lane >> 2);
                unsigned bh[2] = {Bh[kr][nb], Bh[kr+4][nb]};
                unsigned bl[2] = {Bl[kr][nb], Bl[kr+4][nb]};
                #pragma unroll
                for (int i = 0; i < 2; i++) {
                    mma8(acc[i][j], al[i], bh);
                    mma8(acc[i][j], ah[i], bl);
                    mma8(acc[i][j], ah[i], bh);
                }
            }
        }
        __syncthreads();
    }
    #pragma unroll
    for (int j = 0; j < 8; j++) {
        int c = col0 + wn + j * 8 + (lane & 3) * 2;
        float2 bb = *(const float2*)&bias[c];
        #pragma unroll
        for (int i = 0; i < 2; i++) {
            size_t r = row0 + wm + i * 16 + (lane >> 2);
            float2 o0 = {acc[i][j][0] + bb.x, acc[i][j][1] + bb.y};
            float2 o1 = {acc[i][j][2] + bb.x, acc[i][j][3] + bb.y};
            *(float2*)&C[r * DMODEL + c]       = o0;
            *(float2*)&C[(r + 8) * DMODEL + c] = o1;
        }
    }
}

// ---------------------------------------------------------------------------
// Scores (3xTF32): per (b,h), S = Q@K^T * 0.125, masked -> attn.
// block 128x128, K=64.
// ---------------------------------------------------------------------------
__global__ __launch_bounds__(256, 2)
void scores_mma(const float* __restrict__ gq, const float* __restrict__ gk,
                const int* __restrict__ mask, float* __restrict__ attn) {
    __shared__ unsigned Ah[16][136], Al[16][136];
    __shared__ unsigned Bh[16][136], Bl[16][136];
    const int tid = threadIdx.x, lane = tid & 31, warp = tid >> 5;
    const int wm = (warp & 3) * 32, wn = (warp >> 2) * 64;
    const int bh_i = blockIdx.z, b = bh_i >> 4, h = bh_i & 15;
    const int q0 = blockIdx.y * 128, c0 = blockIdx.x * 128;
    const float* Qb = gq + (size_t)b * SEQ * DMODEL + h * DHEAD;
    const float* Kb = gk + (size_t)b * SEQ * DMODEL + h * DHEAD;

    float acc[2][8][4] = {};
    #pragma unroll
    for (int k0 = 0; k0 < DHEAD; k0 += 16) {
        #pragma unroll
        for (int l = 0; l < 2; l++) {
            int idx = tid + l * 256, r = idx >> 2, kc = (idx & 3) << 2;
            float4 a4 = *(const float4*)&Qb[(size_t)(q0 + r) * DMODEL + k0 + kc];
            float4 b4 = *(const float4*)&Kb[(size_t)(c0 + r) * DMODEL + k0 + kc];
            split2(a4.x, Ah[kc+0][r], Al[kc+0][r]); split2(a4.y, Ah[kc+1][r], Al[kc+1][r]);
            split2(a4.z, Ah[kc+2][r], Al[kc+2][r]); split2(a4.w, Ah[kc+3][r], Al[kc+3][r]);
            split2(b4.x, Bh[kc+0][r], Bl[kc+0][r]); split2(b4.y, Bh[kc+1][r], Bl[kc+1][r]);
            split2(b4.z, Bh[kc+2][r], Bl[kc+2][r]); split2(b4.w, Bh[kc+3][r], Bl[kc+3][r]);
        }
        __syncthreads();
        #pragma unroll
        for (int kk = 0; kk < 16; kk += 8) {
            const int kr = kk + (lane & 3), m0 = wm + (lane >> 2);
            unsigned ah[2][4], al[2][4];
            #pragma unroll
            for (int i = 0; i < 2; i++) {
                ah[i][0]=Ah[kr][m0+i*16];   ah[i][1]=Ah[kr][m0+i*16+8];
                ah[i][2]=Ah[kr+4][m0+i*16]; ah[i][3]=Ah[kr+4][m0+i*16+8];
                al[i][0]=Al[kr][m0+i*16];   al[i][1]=Al[kr][m0+i*16+8];
                al[i][2]=Al[kr+4][m0+i*16]; al[i][3]=Al[kr+4][m0+i*16+8];
            }
            #pragma unroll
            for (int j = 0; j < 8; j++) {
                int nb = wn + j * 8 + (lane >> 2);
                unsigned bh2[2] = {Bh[kr][nb], Bh[kr+4][nb]};
                unsigned bl2[2] = {Bl[kr][nb], Bl[kr+4][nb]};
                #pragma unroll
                for (int i = 0; i < 2; i++) {
                    mma8(acc[i][j], al[i], bh2);
                    mma8(acc[i][j], ah[i], bl2);
                    mma8(acc[i][j], ah[i], bh2);
                }
            }
        }
        __syncthreads();
    }
    const int* mrow = mask + (size_t)b * SEQ * SEQ;
    float* out = attn + (size_t)bh_i * SEQ * SEQ;
    #pragma unroll
    for (int j = 0; j < 8; j++) {
        int c = c0 + wn + j * 8 + (lane & 3) * 2;
        #pragma unroll
        for (int i = 0; i < 2; i++) {
            size_t r = q0 + wm + i * 16 + (lane >> 2);
            int2 m0v = *(const int2*)&mrow[r * SEQ + c];
            int2 m1v = *(const int2*)&mrow[(r + 8) * SEQ + c];
            float2 o0, o1;
            o0.x = m0v.x ? acc[i][j][0] * 0.125f : -1e9f;
            o0.y = m0v.y ? acc[i][j][1] * 0.125f : -1e9f;
            o1.x = m1v.x ? acc[i][j][2] * 0.125f : -1e9f;
            o1.y = m1v.y ? acc[i][j][3] * 0.125f : -1e9f;
            *(float2*)&out[r * SEQ + c]       = o0;
            *(float2*)&out[(r + 8) * SEQ + c] = o1;
        }
    }
}

// ---------------------------------------------------------------------------
// Row softmax in place. One block per row, 256 threads, float4.
// ---------------------------------------------------------------------------
__global__ void softmax_kernel(float* __restrict__ attn) {
    float4* p = reinterpret_cast<float4*>(attn + blockIdx.x * (size_t)SEQ);
    const int t = threadIdx.x;
    __shared__ float sred[8];

    float4 v0 = p[t], v1 = p[t + 256];
    float mx = fmaxf(fmaxf(fmaxf(v0.x, v0.y), fmaxf(v0.z, v0.w)),
                     fmaxf(fmaxf(v1.x, v1.y), fmaxf(v1.z, v1.w)));
    #pragma unroll
    for (int o = 16; o > 0; o >>= 1)
        mx = fmaxf(mx, __shfl_xor_sync(0xffffffffu, mx, o));
    if ((t & 31) == 0) sred[t >> 5] = mx;
    __syncthreads();
    float m = sred[0];
    #pragma unroll
    for (int i = 1; i < 8; i++) m = fmaxf(m, sred[i]);
    __syncthreads();

    v0.x = __expf(v0.x - m); v0.y = __expf(v0.y - m);
    v0.z = __expf(v0.z - m); v0.w = __expf(v0.w - m);
    v1.x = __expf(v1.x - m); v1.y = __expf(v1.y - m);
    v1.z = __expf(v1.z - m); v1.w = __expf(v1.w - m);
    float s = v0.x + v0.y + v0.z + v0.w + v1.x + v1.y + v1.z + v1.w;
    #pragma unroll
    for (int o = 16; o > 0; o >>= 1)
        s += __shfl_xor_sync(0xffffffffu, s, o);
    if ((t & 31) == 0) sred[t >> 5] = s;
    __syncthreads();
    float tot = 0.f;
    #pragma unroll
    for (int i = 0; i < 8; i++) tot += sred[i];
    float inv = 1.0f / tot;
    v0.x *= inv; v0.y *= inv; v0.z *= inv; v0.w *= inv;
    v1.x *= inv; v1.y *= inv; v1.z *= inv; v1.w *= inv;
    p[t] = v0; p[t + 256] = v1;
}

// ---------------------------------------------------------------------------
// PV (1xTF32): ctx[S,64] = P[S,S] @ V[S,64]. block 128x64, BK=16.
// warps 4(M)x2(N), warp tile 32x32.
// ---------------------------------------------------------------------------
__global__ __launch_bounds__(256, 2)
void pv_mma(const float* __restrict__ attn, const float* __restrict__ gv,
            float* __restrict__ gctx) {
    __shared__ unsigned Ps[16][136];
    __shared__ unsigned Vs[16][72];
    const int tid = threadIdx.x, lane = tid & 31, warp = tid >> 5;
    const int wm = (warp & 3) * 32, wn = (warp >> 2) * 32;
    const int bh_i = blockIdx.z, b = bh_i >> 4, h = bh_i & 15;
    const float* P = attn + (size_t)bh_i * SEQ * SEQ;
    const float* V = gv + (size_t)b * SEQ * DMODEL + h * DHEAD;
    float* Cc = gctx + (size_t)b * SEQ * DMODEL + h * DHEAD;
    const int q0 = blockIdx.y * 128;

    float acc[2][4][4] = {};
    for (int k0 = 0; k0 < SEQ; k0 += 16) {
        #pragma unroll
        for (int l = 0; l < 2; l++) {
            int idx = tid + l * 256, r = idx >> 2, kc = (idx & 3) << 2;
            float4 a4 = *(const float4*)&P[(size_t)(q0 + r) * SEQ + k0 + kc];
            Ps[kc+0][r]=f2tf(a4.x); Ps[kc+1][r]=f2tf(a4.y); Ps[kc+2][r]=f2tf(a4.z); Ps[kc+3][r]=f2tf(a4.w);
        }
        {
            int kk = tid >> 4, c = (tid & 15) << 2;
            float4 b4 = *(const float4*)&V[(size_t)(k0 + kk) * DMODEL + c];
            Vs[kk][c+0]=f2tf(b4.x); Vs[kk][c+1]=f2tf(b4.y); Vs[kk][c+2]=f2tf(b4.z); Vs[kk][c+3]=f2tf(b4.w);
        }
        __syncthreads();
        #pragma unroll
        for (int kk = 0; kk < 16; kk += 8) {
            const int kr = kk + (lane & 3), m0 = wm + (lane >> 2);
            unsigned af[2][4];
            #pragma unroll
            for (int i = 0; i < 2; i++) {
                af[i][0]=Ps[kr][m0+i*16];   af[i][1]=Ps[kr][m0+i*16+8];
                af[i][2]=Ps[kr+4][m0+i*16]; af[i][3]=Ps[kr+4][m0+i*16+8];
            }
            #pragma unroll
            for (int j = 0; j < 4; j++) {
                int nb = wn + j * 8 + (lane >> 2);
                unsigned bf[2] = {Vs[kr][nb], Vs[kr+4][nb]};
                mma8(acc[0][j], af[0], bf);
                mma8(acc[1][j], af[1], bf);
            }
        }
        __syncthreads();
    }
    #pragma unroll
    for (int j = 0; j < 4; j++) {
        int c = wn + j * 8 + (lane & 3) * 2;
        #pragma unroll
        for (int i = 0; i < 2; i++) {
            size_t r = q0 + wm + i * 16 + (lane >> 2);
            float2 o0 = {acc[i][j][0], acc[i][j][1]};
            float2 o1 = {acc[i][j][2], acc[i][j][3]};
            *(float2*)&Cc[r * DMODEL + c]       = o0;
            *(float2*)&Cc[(r + 8) * DMODEL + c] = o1;
        }
    }
}

// ---------------------------------------------------------------------------
// Residual + LayerNorm.
// ---------------------------------------------------------------------------
__global__ void ln_kernel(const float* __restrict__ resid,
                          const float* __restrict__ x,
                          const float* __restrict__ gamma,
                          const float* __restrict__ beta,
                          float* __restrict__ out) {
    const size_t row = blockIdx.x;
    const float4* xr = reinterpret_cast<const float4*>(x + row * DMODEL);
    const float4* rr = reinterpret_cast<const float4*>(resid + row * DMODEL);
    const int t = threadIdx.x;
    __shared__ float sred[8];

    float4 a = rr[t], bv = xr[t];
    float4 v = {a.x + bv.x, a.y + bv.y, a.z + bv.z, a.w + bv.w};
    float s = v.x + v.y + v.z + v.w;
    #pragma unroll
    for (int o = 16; o > 0; o >>= 1) s += __shfl_xor_sync(0xffffffffu, s, o);
    if ((t & 31) == 0) sred[t >> 5] = s;
    __syncthreads();
    float tot = 0.f;
    #pragma unroll
    for (int i = 0; i < 8; i++) tot += sred[i];
    const float mu = tot * (1.0f / DMODEL);
    __syncthreads();

    float dx = v.x - mu, dy = v.y - mu, dz = v.z - mu, dw = v.w - mu;
    float sq = dx*dx + dy*dy + dz*dz + dw*dw;
    #pragma unroll
    for (int o = 16; o > 0; o >>= 1) sq += __shfl_xor_sync(0xffffffffu, sq, o);
    if ((t & 31) == 0) sred[t >> 5] = sq;
    __syncthreads();
    float tot2 = 0.f;
    #pragma unroll
    for (int i = 0; i < 8; i++) tot2 += sred[i];
    const float inv = rsqrtf(tot2 * (1.0f / DMODEL) + 1e-5f);

    float4 g = reinterpret_cast<const float4*>(gamma)[t];
    float4 be = reinterpret_cast<const float4*>(beta)[t];
    float4 o;
    o.x = dx * inv * g.x + be.x;
    o.y = dy * inv * g.y + be.y;
    o.z = dz * inv * g.z + be.z;
    o.w = dw * inv * g.w + be.w;
    reinterpret_cast<float4*>(out + row * DMODEL)[t] = o;
}

// ---------------------------------------------------------------------------
extern "C" void kernel_launch(void* const* d_in, const int* in_sizes, int n_in,
                              void* d_out, int out_size) {
    const float* q     = (const float*)d_in[0];
    const float* k     = (const float*)d_in[1];
    const float* v     = (const float*)d_in[2];
    const int*   mask  = (const int*)  d_in[3];
    const float* wq    = (const float*)d_in[4];
    const float* bq    = (const float*)d_in[5];
    const float* wk    = (const float*)d_in[6];
    const float* bk    = (const float*)d_in[7];
    const float* wv    = (const float*)d_in[8];
    const float* bv    = (const float*)d_in[9];
    const float* wo    = (const float*)d_in[10];
    const float* bo    = (const float*)d_in[11];
    const float* gamma = (const float*)d_in[12];
    const float* beta  = (const float*)d_in[13];

    float* out  = (float*)d_out;
    float* attn = out + ATT_OFF;

    void* sp = nullptr;
    cudaGetSymbolAddress(&sp, g_scratch);
    float* gq   = (float*)sp;
    float* gk   = gq   + (size_t)MROWS * DMODEL;
    float* gv   = gk   + (size_t)MROWS * DMODEL;
    float* gctx = gv   + (size_t)MROWS * DMODEL;
    float* go   = gctx + (size_t)MROWS * DMODEL;

    dim3 gProj(DMODEL / 128, MROWS / 128);              // (8, 32)
    gemm_nt_tf32x3<<<gProj, 256>>>(q, wq, bq, gq);      // high-precision q
    gemm_nt_tf32x3<<<gProj, 256>>>(k, wk, bk, gk);      // high-precision k
    gemm_nt_tf32<<<gProj, 256>>>(v, wv, bv, gv);

    dim3 gScores(SEQ / 128, SEQ / 128, BATCH * NHEADS); // (16, 16, 32)
    scores_mma<<<gScores, 256>>>(gq, gk, mask, attn);

    softmax_kernel<<<BATCH * NHEADS * SEQ, 256>>>(attn);

    dim3 gPV(1, SEQ / 128, BATCH * NHEADS);             // (1, 16, 32)
    pv_mma<<<gPV, 256>>>(attn, gv, gctx);

    gemm_nt_tf32<<<gProj, 256>>>(gctx, wo, bo, go);

    ln_kernel<<<MROWS, 256>>>(q, go, gamma, beta, out);
}

// round 4
// speedup vs baseline: 1.9987x; 1.0245x over previous
#include <cuda_runtime.h>
#include <cuda_bf16.h>
#include <math.h>

#define BATCH 2
#define SEQ   2048
#define DMODEL 1024
#define NHEADS 16
#define DHEAD  64
#define MROWS (BATCH*SEQ)                    // 4096
#define ATT_OFF ((size_t)BATCH*SEQ*DMODEL)
#define NKT 16                               // key tiles in scores grid

// 5 matrices of scratch + rowsum partials [bh][row][ktile]
__device__ float g_scratch[5ull * MROWS * DMODEL + (size_t)BATCH * NHEADS * SEQ * NKT];

// ---------------------------------------------------------------------------
__device__ __forceinline__ unsigned f2tf(float x) {
    unsigned r;
    asm("cvt.rna.tf32.f32 %0, %1;" : "=r"(r) : "f"(x));
    return r;
}
__device__ __forceinline__ void split2(float x, unsigned& hi, unsigned& lo) {
    hi = f2tf(x);
    lo = f2tf(x - __uint_as_float(hi));
}
__device__ __forceinline__ void mma8(float* d, const unsigned* a, const unsigned* b) {
    asm volatile(
        "mma.sync.aligned.m16n8k8.row.col.f32.tf32.tf32.f32 "
        "{%0,%1,%2,%3}, {%4,%5,%6,%7}, {%8,%9}, {%0,%1,%2,%3};"
        : "+f"(d[0]), "+f"(d[1]), "+f"(d[2]), "+f"(d[3])
        : "r"(a[0]), "r"(a[1]), "r"(a[2]), "r"(a[3]), "r"(b[0]), "r"(b[1]));
}

// ---------------------------------------------------------------------------
// 1x TF32 NT GEMM + bias. block 128x128, BK=16, 256 thr.
// ---------------------------------------------------------------------------
__global__ __launch_bounds__(256, 2)
void gemm_nt_tf32(const float* __restrict__ A, const float* __restrict__ W,
                  const float* __restrict__ bias, float* __restrict__ C) {
    __shared__ unsigned As[16][136];
    __shared__ unsigned Bs[16][136];
    const int tid = threadIdx.x, lane = tid & 31, warp = tid >> 5;
    const int wm = (warp & 3) * 32, wn = (warp >> 2) * 64;
    const int row0 = blockIdx.y * 128, col0 = blockIdx.x * 128;

    float acc[2][8][4] = {};
    for (int k0 = 0; k0 < DMODEL; k0 += 16) {
        #pragma unroll
        for (int l = 0; l < 2; l++) {
            int idx = tid + l * 256, r = idx >> 2, kc = (idx & 3) << 2;
            float4 a4 = *(const float4*)&A[(size_t)(row0 + r) * DMODEL + k0 + kc];
            float4 b4 = *(const float4*)&W[(size_t)(col0 + r) * DMODEL + k0 + kc];
            As[kc+0][r]=f2tf(a4.x); As[kc+1][r]=f2tf(a4.y); As[kc+2][r]=f2tf(a4.z); As[kc+3][r]=f2tf(a4.w);
            Bs[kc+0][r]=f2tf(b4.x); Bs[kc+1][r]=f2tf(b4.y); Bs[kc+2][r]=f2tf(b4.z); Bs[kc+3][r]=f2tf(b4.w);
        }
        __syncthreads();
        #pragma unroll
        for (int kk = 0; kk < 16; kk += 8) {
            const int kr = kk + (lane & 3), m0 = wm + (lane >> 2);
            unsigned af[2][4];
            #pragma unroll
            for (int i = 0; i < 2; i++) {
                af[i][0] = As[kr][m0 + i*16];     af[i][1] = As[kr][m0 + i*16 + 8];
                af[i][2] = As[kr+4][m0 + i*16];   af[i][3] = As[kr+4][m0 + i*16 + 8];
            }
            #pragma unroll
            for (int j = 0; j < 8; j++) {
                int nb = wn + j * 8 + (lane >> 2);
                unsigned bf[2] = {Bs[kr][nb], Bs[kr+4][nb]};
                mma8(acc[0][j], af[0], bf);
                mma8(acc[1][j], af[1], bf);
            }
        }
        __syncthreads();
    }
    #pragma unroll
    for (int j = 0; j < 8; j++) {
        int c = col0 + wn + j * 8 + (lane & 3) * 2;
        float2 bb = *(const float2*)&bias[c];
        #pragma unroll
        for (int i = 0; i < 2; i++) {
            size_t r = row0 + wm + i * 16 + (lane >> 2);
            float2 o0 = {acc[i][j][0] + bb.x, acc[i][j][1] + bb.y};
            float2 o1 = {acc[i][j][2] + bb.x, acc[i][j][3] + bb.y};
            *(float2*)&C[r * DMODEL + c]       = o0;
            *(float2*)&C[(r + 8) * DMODEL + c] = o1;
        }
    }
}

// ---------------------------------------------------------------------------
// 3xTF32 q+k projections batched on blockIdx.z.
// ---------------------------------------------------------------------------
__global__ __launch_bounds__(256, 2)
void gemm_qk_tf32x3(const float* __restrict__ qin, const float* __restrict__ kin,
                    const float* __restrict__ wq, const float* __restrict__ wk,
                    const float* __restrict__ bq, const float* __restrict__ bk,
                    float* __restrict__ gq, float* __restrict__ gk) {
    const float* A    = blockIdx.z ? kin : qin;
    const float* W    = blockIdx.z ? wk  : wq;
    const float* bias = blockIdx.z ? bk  : bq;
    float* C          = blockIdx.z ? gk  : gq;

    __shared__ unsigned Ah[16][136], Al[16][136];
    __shared__ unsigned Bh[16][136], Bl[16][136];
    const int tid = threadIdx.x, lane = tid & 31, warp = tid >> 5;
    const int wm = (warp & 3) * 32, wn = (warp >> 2) * 64;
    const int row0 = blockIdx.y * 128, col0 = blockIdx.x * 128;

    float acc[2][8][4] = {};
    for (int k0 = 0; k0 < DMODEL; k0 += 16) {
        #pragma unroll
        for (int l = 0; l < 2; l++) {
            int idx = tid + l * 256, r = idx >> 2, kc = (idx & 3) << 2;
            float4 a4 = *(const float4*)&A[(size_t)(row0 + r) * DMODEL + k0 + kc];
            float4 b4 = *(const float4*)&W[(size_t)(col0 + r) * DMODEL + k0 + kc];
            split2(a4.x, Ah[kc+0][r], Al[kc+0][r]); split2(a4.y, Ah[kc+1][r], Al[kc+1][r]);
            split2(a4.z, Ah[kc+2][r], Al[kc+2][r]); split2(a4.w, Ah[kc+3][r], Al[kc+3][r]);
            split2(b4.x, Bh[kc+0][r], Bl[kc+0][r]); split2(b4.y, Bh[kc+1][r], Bl[kc+1][r]);
            split2(b4.z, Bh[kc+2][r], Bl[kc+2][r]); split2(b4.w, Bh[kc+3][r], Bl[kc+3][r]);
        }
        __syncthreads();
        #pragma unroll
        for (int kk = 0; kk < 16; kk += 8) {
            const int kr = kk + (lane & 3), m0 = wm + (lane >> 2);
            unsigned ah[2][4], al[2][4];
            #pragma unroll
            for (int i = 0; i < 2; i++) {
                ah[i][0]=Ah[kr][m0+i*16];   ah[i][1]=Ah[kr][m0+i*16+8];
                ah[i][2]=Ah[kr+4][m0+i*16]; ah[i][3]=Ah[kr+4][m0+i*16+8];
                al[i][0]=Al[kr][m0+i*16];   al[i][1]=Al[kr][m0+i*16+8];
                al[i][2]=Al[kr+4][m0+i*16]; al[i][3]=Al[kr+4][m0+i*16+8];
            }
            #pragma unroll
            for (int j = 0; j < 8; j++) {
                int nb = wn + j * 8 + (lane >> 2);
                unsigned bh[2] = {Bh[kr][nb], Bh[kr+4][nb]};
                unsigned bl[2] = {Bl[kr][nb], Bl[kr+4][nb]};
                #pragma unroll
                for (int i = 0; i < 2; i++) {
                    mma8(acc[i][j], al[i], bh);
                    mma8(acc[i][j], ah[i], bl);
                    mma8(acc[i][j], ah[i], bh);
                }
            }
        }
        __syncthreads();
    }
    #pragma unroll
    for (int j = 0; j < 8; j++) {
        int c = col0 + wn + j * 8 + (lane & 3) * 2;
        float2 bb = *(const float2*)&bias[c];
        #pragma unroll
        for (int i = 0; i < 2; i++) {
            size_t r = row0 + wm + i * 16 + (lane >> 2);
            float2 o0 = {acc[i][j][0] + bb.x, acc[i][j][1] + bb.y};
            float2 o1 = {acc[i][j][2] + bb.x, acc[i][j][3] + bb.y};
            *(float2*)&C[r * DMODEL + c]       = o0;
            *(float2*)&C[(r + 8) * DMODEL + c] = o1;
        }
    }
}

// ---------------------------------------------------------------------------
// Fused scores (3xTF32) + mask + exp (no max-sub) -> unnormalized P + rowsum
// partials. grid (NKT, 16, 32).
// ---------------------------------------------------------------------------
__global__ __launch_bounds__(256, 2)
void scores_exp(const float* __restrict__ gq, const float* __restrict__ gk,
                const int* __restrict__ mask, float* __restrict__ attn,
                float* __restrict__ partial) {
    __shared__ unsigned Ah[16][136], Al[16][136];
    __shared__ unsigned Bh[16][136], Bl[16][136];
    __shared__ float sums[2][128];
    const int tid = threadIdx.x, lane = tid & 31, warp = tid >> 5;
    const int wm = (warp & 3) * 32, wn = (warp >> 2) * 64;
    const int bh_i = blockIdx.z, b = bh_i >> 4, h = bh_i & 15;
    const int q0 = blockIdx.y * 128, c0 = blockIdx.x * 128;
    const float* Qb = gq + (size_t)b * SEQ * DMODEL + h * DHEAD;
    const float* Kb = gk + (size_t)b * SEQ * DMODEL + h * DHEAD;

    float acc[2][8][4] = {};
    #pragma unroll
    for (int k0 = 0; k0 < DHEAD; k0 += 16) {
        #pragma unroll
        for (int l = 0; l < 2; l++) {
            int idx = tid + l * 256, r = idx >> 2, kc = (idx & 3) << 2;
            float4 a4 = *(const float4*)&Qb[(size_t)(q0 + r) * DMODEL + k0 + kc];
            float4 b4 = *(const float4*)&Kb[(size_t)(c0 + r) * DMODEL + k0 + kc];
            split2(a4.x, Ah[kc+0][r], Al[kc+0][r]); split2(a4.y, Ah[kc+1][r], Al[kc+1][r]);
            split2(a4.z, Ah[kc+2][r], Al[kc+2][r]); split2(a4.w, Ah[kc+3][r], Al[kc+3][r]);
            split2(b4.x, Bh[kc+0][r], Bl[kc+0][r]); split2(b4.y, Bh[kc+1][r], Bl[kc+1][r]);
            split2(b4.z, Bh[kc+2][r], Bl[kc+2][r]); split2(b4.w, Bh[kc+3][r], Bl[kc+3][r]);
        }
        __syncthreads();
        #pragma unroll
        for (int kk = 0; kk < 16; kk += 8) {
            const int kr = kk + (lane & 3), m0 = wm + (lane >> 2);
            unsigned ah[2][4], al[2][4];
            #pragma unroll
            for (int i = 0; i < 2; i++) {
                ah[i][0]=Ah[kr][m0+i*16];   ah[i][1]=Ah[kr][m0+i*16+8];
                ah[i][2]=Ah[kr+4][m0+i*16]; ah[i][3]=Ah[kr+4][m0+i*16+8];
                al[i][0]=Al[kr][m0+i*16];   al[i][1]=Al[kr][m0+i*16+8];
                al[i][2]=Al[kr+4][m0+i*16]; al[i][3]=Al[kr+4][m0+i*16+8];
            }
            #pragma unroll
            for (int j = 0; j < 8; j++) {
                int nb = wn + j * 8 + (lane >> 2);
                unsigned bh2[2] = {Bh[kr][nb], Bh[kr+4][nb]};
                unsigned bl2[2] = {Bl[kr][nb], Bl[kr+4][nb]};
                #pragma unroll
                for (int i = 0; i < 2; i++) {
                    mma8(acc[i][j], al[i], bh2);
                    mma8(acc[i][j], ah[i], bl2);
                    mma8(acc[i][j], ah[i], bh2);
                }
            }
        }
        __syncthreads();
    }

    // Epilogue: mask -> exp (unnormalized) -> write P, accumulate row sums.
    const int* mrow = mask + (size_t)b * SEQ * SEQ;
    float* out = attn + (size_t)bh_i * SEQ * SEQ;
    float rs[2][2] = {};
    #pragma unroll
    for (int j = 0; j < 8; j++) {
        int c = c0 + wn + j * 8 + (lane & 3) * 2;
        #pragma unroll
        for (int i = 0; i < 2; i++) {
            size_t r = q0 + wm + i * 16 + (lane >> 2);
            int2 m0v = *(const int2*)&mrow[r * SEQ + c];
            int2 m1v = *(const int2*)&mrow[(r + 8) * SEQ + c];
            float2 o0, o1;
            o0.x = m0v.x ? __expf(acc[i][j][0] * 0.125f) : 0.f;
            o0.y = m0v.y ? __expf(acc[i][j][1] * 0.125f) : 0.f;
            o1.x = m1v.x ? __expf(acc[i][j][2] * 0.125f) : 0.f;
            o1.y = m1v.y ? __expf(acc[i][j][3] * 0.125f) : 0.f;
            *(float2*)&out[r * SEQ + c]       = o0;
            *(float2*)&out[(r + 8) * SEQ + c] = o1;
            rs[i][0] += o0.x + o0.y;
            rs[i][1] += o1.x + o1.y;
        }
    }
    // reduce over the 4 lanes sharing a row (lane&3)
    #pragma unroll
    for (int i = 0; i < 2; i++)
        #pragma unroll
        for (int hh = 0; hh < 2; hh++) {
            float v = rs[i][hh];
            v += __shfl_xor_sync(0xffffffffu, v, 1);
            v += __shfl_xor_sync(0xffffffffu, v, 2);
            if ((lane & 3) == 0)
                sums[warp >> 2][wm + i * 16 + hh * 8 + (lane >> 2)] = v;
        }
    __syncthreads();
    if (tid < 128) {
        float tot = sums[0][tid] + sums[1][tid];
        partial[((size_t)bh_i * SEQ + q0 + tid) * NKT + blockIdx.x] = tot;
    }
}

// ---------------------------------------------------------------------------
// Fused PV (1xTF32) + normalization: reads unnormalized P, scales by inv
// rowsum, writes normalized attention in place, accumulates ctx = P_norm @ V.
// grid (1, 16, 32).
// ---------------------------------------------------------------------------
__global__ __launch_bounds__(256, 2)
void pv_norm(float* __restrict__ attn, const float* __restrict__ gv,
             const float* __restrict__ partial, float* __restrict__ gctx) {
    __shared__ unsigned Ps[16][136];
    __shared__ unsigned Vs[16][72];
    __shared__ float inv_s[128];
    const int tid = threadIdx.x, lane = tid & 31, warp = tid >> 5;
    const int wm = (warp & 3) * 32, wn = (warp >> 2) * 32;
    const int bh_i = blockIdx.z, b = bh_i >> 4, h = bh_i & 15;
    float* P = attn + (size_t)bh_i * SEQ * SEQ;
    const float* V = gv + (size_t)b * SEQ * DMODEL + h * DHEAD;
    float* Cc = gctx + (size_t)b * SEQ * DMODEL + h * DHEAD;
    const int q0 = blockIdx.y * 128;

    if (tid < 128) {
        const float4* pp = (const float4*)&partial[((size_t)bh_i * SEQ + q0 + tid) * NKT];
        float4 p0 = pp[0], p1 = pp[1], p2 = pp[2], p3 = pp[3];
        float s = ((p0.x + p0.y) + (p0.z + p0.w)) + ((p1.x + p1.y) + (p1.z + p1.w))
                + ((p2.x + p2.y) + (p2.z + p2.w)) + ((p3.x + p3.y) + (p3.z + p3.w));
        inv_s[tid] = 1.0f / s;
    }
    __syncthreads();

    float acc[2][4][4] = {};
    for (int k0 = 0; k0 < SEQ; k0 += 16) {
        #pragma unroll
        for (int l = 0; l < 2; l++) {
            int idx = tid + l * 256, r = idx >> 2, kc = (idx & 3) << 2;
            size_t off = (size_t)(q0 + r) * SEQ + k0 + kc;
            float4 a4 = *(const float4*)&P[off];
            float sc = inv_s[r];
            a4.x *= sc; a4.y *= sc; a4.z *= sc; a4.w *= sc;
            *(float4*)&P[off] = a4;   // normalized attention output
            Ps[kc+0][r]=f2tf(a4.x); Ps[kc+1][r]=f2tf(a4.y);
            Ps[kc+2][r]=f2tf(a4.z); Ps[kc+3][r]=f2tf(a4.w);
        }
        {
            int kk = tid >> 4, c = (tid & 15) << 2;
            float4 b4 = *(const float4*)&V[(size_t)(k0 + kk) * DMODEL + c];
            Vs[kk][c+0]=f2tf(b4.x); Vs[kk][c+1]=f2tf(b4.y);
            Vs[kk][c+2]=f2tf(b4.z); Vs[kk][c+3]=f2tf(b4.w);
        }
        __syncthreads();
        #pragma unroll
        for (int kk = 0; kk < 16; kk += 8) {
            const int kr = kk + (lane & 3), m0 = wm + (lane >> 2);
            unsigned af[2][4];
            #pragma unroll
            for (int i = 0; i < 2; i++) {
                af[i][0]=Ps[kr][m0+i*16];   af[i][1]=Ps[kr][m0+i*16+8];
                af[i][2]=Ps[kr+4][m0+i*16]; af[i][3]=Ps[kr+4][m0+i*16+8];
            }
            #pragma unroll
            for (int j = 0; j < 4; j++) {
                int nb = wn + j * 8 + (lane >> 2);
                unsigned bf[2] = {Vs[kr][nb], Vs[kr+4][nb]};
                mma8(acc[0][j], af[0], bf);
                mma8(acc[1][j], af[1], bf);
            }
        }
        __syncthreads();
    }
    #pragma unroll
    for (int j = 0; j < 4; j++) {
        int c = wn + j * 8 + (lane & 3) * 2;
        #pragma unroll
        for (int i = 0; i < 2; i++) {
            size_t r = q0 + wm + i * 16 + (lane >> 2);
            float2 o0 = {acc[i][j][0], acc[i][j][1]};
            float2 o1 = {acc[i][j][2], acc[i][j][3]};
            *(float2*)&Cc[r * DMODEL + c]       = o0;
            *(float2*)&Cc[(r + 8) * DMODEL + c] = o1;
        }
    }
}

// ---------------------------------------------------------------------------
// Residual + LayerNorm.
// ---------------------------------------------------------------------------
__global__ void ln_kernel(const float* __restrict__ resid,
                          const float* __restrict__ x,
                          const float* __restrict__ gamma,
                          const float* __restrict__ beta,
                          float* __restrict__ out) {
    const size_t row = blockIdx.x;
    const float4* xr = reinterpret_cast<const float4*>(x + row * DMODEL);
    const float4* rr = reinterpret_cast<const float4*>(resid + row * DMODEL);
    const int t = threadIdx.x;
    __shared__ float sred[8];

    float4 a = rr[t], bv = xr[t];
    float4 v = {a.x + bv.x, a.y + bv.y, a.z + bv.z, a.w + bv.w};
    float s = v.x + v.y + v.z + v.w;
    #pragma unroll
    for (int o = 16; o > 0; o >>= 1) s += __shfl_xor_sync(0xffffffffu, s, o);
    if ((t & 31) == 0) sred[t >> 5] = s;
    __syncthreads();
    float tot = 0.f;
    #pragma unroll
    for (int i = 0; i < 8; i++) tot += sred[i];
    const float mu = tot * (1.0f / DMODEL);
    __syncthreads();

    float dx = v.x - mu, dy = v.y - mu, dz = v.z - mu, dw = v.w - mu;
    float sq = dx*dx + dy*dy + dz*dz + dw*dw;
    #pragma unroll
    for (int o = 16; o > 0; o >>= 1) sq += __shfl_xor_sync(0xffffffffu, sq, o);
    if ((t & 31) == 0) sred[t >> 5] = sq;
    __syncthreads();
    float tot2 = 0.f;
    #pragma unroll
    for (int i = 0; i < 8; i++) tot2 += sred[i];
    const float inv = rsqrtf(tot2 * (1.0f / DMODEL) + 1e-5f);

    float4 g = reinterpret_cast<const float4*>(gamma)[t];
    float4 be = reinterpret_cast<const float4*>(beta)[t];
    float4 o;
    o.x = dx * inv * g.x + be.x;
    o.y = dy * inv * g.y + be.y;
    o.z = dz * inv * g.z + be.z;
    o.w = dw * inv * g.w + be.w;
    reinterpret_cast<float4*>(out + row * DMODEL)[t] = o;
}

// ---------------------------------------------------------------------------
extern "C" void kernel_launch(void* const* d_in, const int* in_sizes, int n_in,
                              void* d_out, int out_size) {
    const float* q     = (const float*)d_in[0];
    const float* k     = (const float*)d_in[1];
    const float* v     = (const float*)d_in[2];
    const int*   mask  = (const int*)  d_in[3];
    const float* wq    = (const float*)d_in[4];
    const float* bq    = (const float*)d_in[5];
    const float* wk    = (const float*)d_in[6];
    const float* bk    = (const float*)d_in[7];
    const float* wv    = (const float*)d_in[8];
    const float* bv    = (const float*)d_in[9];
    const float* wo    = (const float*)d_in[10];
    const float* bo    = (const float*)d_in[11];
    const float* gamma = (const float*)d_in[12];
    const float* beta  = (const float*)d_in[13];

    float* out  = (float*)d_out;
    float* attn = out + ATT_OFF;

    void* sp = nullptr;
    cudaGetSymbolAddress(&sp, g_scratch);
    float* gq      = (float*)sp;
    float* gk      = gq   + (size_t)MROWS * DMODEL;
    float* gv      = gk   + (size_t)MROWS * DMODEL;
    float* gctx    = gv   + (size_t)MROWS * DMODEL;
    float* go      = gctx + (size_t)MROWS * DMODEL;
    float* partial = go   + (size_t)MROWS * DMODEL;

    dim3 gQK(DMODEL / 128, MROWS / 128, 2);             // (8, 32, 2)
    gemm_qk_tf32x3<<<gQK, 256>>>(q, k, wq, wk, bq, bk, gq, gk);

    dim3 gProj(DMODEL / 128, MROWS / 128);              // (8, 32)
    gemm_nt_tf32<<<gProj, 256>>>(v, wv, bv, gv);

    dim3 gScores(NKT, SEQ / 128, BATCH * NHEADS);       // (16, 16, 32)
    scores_exp<<<gScores, 256>>>(gq, gk, mask, attn, partial);

    dim3 gPV(1, SEQ / 128, BATCH * NHEADS);             // (1, 16, 32)
    pv_norm<<<gPV, 256>>>(attn, gv, partial, gctx);

    gemm_nt_tf32<<<gProj, 256>>>(gctx, wo, bo, go);

    ln_kernel<<<MROWS, 256>>>(q, go, gamma, beta, out);
}

// round 5
// speedup vs baseline: 2.3814x; 1.1915x over previous
#include <cuda_runtime.h>
#include <cuda_bf16.h>
#include <math.h>

#define BATCH 2
#define SEQ   2048
#define DMODEL 1024
#define NHEADS 16
#define DHEAD  64
#define MROWS (BATCH*SEQ)                    // 4096
#define ATT_OFF ((size_t)BATCH*SEQ*DMODEL)
#define NKT 16                               // key tiles in scores grid
#define SPLITK 4                             // pv split-K factor

// gq, gk, gv, go (4 x 4M) + pctx (4 x 4M) + rowsum partials (1M)
__device__ float g_scratch[8ull * MROWS * DMODEL + (size_t)BATCH * NHEADS * SEQ * NKT];

// ---------------------------------------------------------------------------
__device__ __forceinline__ unsigned f2tf(float x) {
    unsigned r;
    asm("cvt.rna.tf32.f32 %0, %1;" : "=r"(r) : "f"(x));
    return r;
}
__device__ __forceinline__ void mma8(float* d, const unsigned* a, const unsigned* b) {
    asm volatile(
        "mma.sync.aligned.m16n8k8.row.col.f32.tf32.tf32.f32 "
        "{%0,%1,%2,%3}, {%4,%5,%6,%7}, {%8,%9}, {%0,%1,%2,%3};"
        : "+f"(d[0]), "+f"(d[1]), "+f"(d[2]), "+f"(d[3])
        : "r"(a[0]), "r"(a[1]), "r"(a[2]), "r"(a[3]), "r"(b[0]), "r"(b[1]));
}
__device__ __forceinline__ void mma16(float* d, const unsigned* a, const unsigned* b) {
    asm volatile(
        "mma.sync.aligned.m16n8k16.row.col.f32.bf16.bf16.f32 "
        "{%0,%1,%2,%3}, {%4,%5,%6,%7}, {%8,%9}, {%0,%1,%2,%3};"
        : "+f"(d[0]), "+f"(d[1]), "+f"(d[2]), "+f"(d[3])
        : "r"(a[0]), "r"(a[1]), "r"(a[2]), "r"(a[3]), "r"(b[0]), "r"(b[1]));
}
// split x,y into bf16 hi/lo pairs packed along k (x in low half)
__device__ __forceinline__ void splitbf2(float x, float y, unsigned& hi, unsigned& lo) {
    __nv_bfloat16 hx = __float2bfloat16_rn(x);
    __nv_bfloat16 hy = __float2bfloat16_rn(y);
    __nv_bfloat16 lx = __float2bfloat16_rn(x - __bfloat162float(hx));
    __nv_bfloat16 ly = __float2bfloat16_rn(y - __bfloat162float(hy));
    hi = (unsigned)__bfloat16_as_ushort(hx) | ((unsigned)__bfloat16_as_ushort(hy) << 16);
    lo = (unsigned)__bfloat16_as_ushort(lx) | ((unsigned)__bfloat16_as_ushort(ly) << 16);
}

// ---------------------------------------------------------------------------
// 1x TF32 NT GEMM + bias (v projection). block 128x128, BK=16, 256 thr.
// ---------------------------------------------------------------------------
__global__ __launch_bounds__(256, 2)
void gemm_nt_tf32(const float* __restrict__ A, const float* __restrict__ W,
                  const float* __restrict__ bias, float* __restrict__ C) {
    __shared__ unsigned As[16][136];
    __shared__ unsigned Bs[16][136];
    const int tid = threadIdx.x, lane = tid & 31, warp = tid >> 5;
    const int wm = (warp & 3) * 32, wn = (warp >> 2) * 64;
    const int row0 = blockIdx.y * 128, col0 = blockIdx.x * 128;

    float acc[2][8][4] = {};
    for (int k0 = 0; k0 < DMODEL; k0 += 16) {
        #pragma unroll
        for (int l = 0; l < 2; l++) {
            int idx = tid + l * 256, r = idx >> 2, kc = (idx & 3) << 2;
            float4 a4 = *(const float4*)&A[(size_t)(row0 + r) * DMODEL + k0 + kc];
            float4 b4 = *(const float4*)&W[(size_t)(col0 + r) * DMODEL + k0 + kc];
            As[kc+0][r]=f2tf(a4.x); As[kc+1][r]=f2tf(a4.y); As[kc+2][r]=f2tf(a4.z); As[kc+3][r]=f2tf(a4.w);
            Bs[kc+0][r]=f2tf(b4.x); Bs[kc+1][r]=f2tf(b4.y); Bs[kc+2][r]=f2tf(b4.z); Bs[kc+3][r]=f2tf(b4.w);
        }
        __syncthreads();
        #pragma unroll
        for (int kk = 0; kk < 16; kk += 8) {
            const int kr = kk + (lane & 3), m0 = wm + (lane >> 2);
            unsigned af[2][4];
            #pragma unroll
            for (int i = 0; i < 2; i++) {
                af[i][0] = As[kr][m0 + i*16];     af[i][1] = As[kr][m0 + i*16 + 8];
                af[i][2] = As[kr+4][m0 + i*16];   af[i][3] = As[kr+4][m0 + i*16 + 8];
            }
            #pragma unroll
            for (int j = 0; j < 8; j++) {
                int nb = wn + j * 8 + (lane >> 2);
                unsigned bf[2] = {Bs[kr][nb], Bs[kr+4][nb]};
                mma8(acc[0][j], af[0], bf);
                mma8(acc[1][j], af[1], bf);
            }
        }
        __syncthreads();
    }
    #pragma unroll
    for (int j = 0; j < 8; j++) {
        int c = col0 + wn + j * 8 + (lane & 3) * 2;
        float2 bb = *(const float2*)&bias[c];
        #pragma unroll
        for (int i = 0; i < 2; i++) {
            size_t r = row0 + wm + i * 16 + (lane >> 2);
            float2 o0 = {acc[i][j][0] + bb.x, acc[i][j][1] + bb.y};
            float2 o1 = {acc[i][j][2] + bb.x, acc[i][j][3] + bb.y};
            *(float2*)&C[r * DMODEL + c]       = o0;
            *(float2*)&C[(r + 8) * DMODEL + c] = o1;
        }
    }
}

// ---------------------------------------------------------------------------
// O projection: A = sum of SPLITK partial ctx buffers, then GEMM + bias.
// ---------------------------------------------------------------------------
__global__ __launch_bounds__(256, 2)
void gemm_o_tf32(const float* __restrict__ pctx, const float* __restrict__ W,
                 const float* __restrict__ bias, float* __restrict__ C) {
    __shared__ unsigned As[16][136];
    __shared__ unsigned Bs[16][136];
    const int tid = threadIdx.x, lane = tid & 31, warp = tid >> 5;
    const int wm = (warp & 3) * 32, wn = (warp >> 2) * 64;
    const int row0 = blockIdx.y * 128, col0 = blockIdx.x * 128;
    const size_t PS = (size_t)MROWS * DMODEL;

    float acc[2][8][4] = {};
    for (int k0 = 0; k0 < DMODEL; k0 += 16) {
        #pragma unroll
        for (int l = 0; l < 2; l++) {
            int idx = tid + l * 256, r = idx >> 2, kc = (idx & 3) << 2;
            size_t off = (size_t)(row0 + r) * DMODEL + k0 + kc;
            float4 a0 = *(const float4*)&pctx[off];
            float4 a1 = *(const float4*)&pctx[off + PS];
            float4 a2 = *(const float4*)&pctx[off + 2*PS];
            float4 a3 = *(const float4*)&pctx[off + 3*PS];
            float4 a4 = {(a0.x+a1.x)+(a2.x+a3.x), (a0.y+a1.y)+(a2.y+a3.y),
                         (a0.z+a1.z)+(a2.z+a3.z), (a0.w+a1.w)+(a2.w+a3.w)};
            float4 b4 = *(const float4*)&W[(size_t)(col0 + r) * DMODEL + k0 + kc];
            As[kc+0][r]=f2tf(a4.x); As[kc+1][r]=f2tf(a4.y); As[kc+2][r]=f2tf(a4.z); As[kc+3][r]=f2tf(a4.w);
            Bs[kc+0][r]=f2tf(b4.x); Bs[kc+1][r]=f2tf(b4.y); Bs[kc+2][r]=f2tf(b4.z); Bs[kc+3][r]=f2tf(b4.w);
        }
        __syncthreads();
        #pragma unroll
        for (int kk = 0; kk < 16; kk += 8) {
            const int kr = kk + (lane & 3), m0 = wm + (lane >> 2);
            unsigned af[2][4];
            #pragma unroll
            for (int i = 0; i < 2; i++) {
                af[i][0] = As[kr][m0 + i*16];     af[i][1] = As[kr][m0 + i*16 + 8];
                af[i][2] = As[kr+4][m0 + i*16];   af[i][3] = As[kr+4][m0 + i*16 + 8];
            }
            #pragma unroll
            for (int j = 0; j < 8; j++) {
                int nb = wn + j * 8 + (lane >> 2);
                unsigned bf[2] = {Bs[kr][nb], Bs[kr+4][nb]};
                mma8(acc[0][j], af[0], bf);
                mma8(acc[1][j], af[1], bf);
            }
        }
        __syncthreads();
    }
    #pragma unroll
    for (int j = 0; j < 8; j++) {
        int c = col0 + wn + j * 8 + (lane & 3) * 2;
        float2 bb = *(const float2*)&bias[c];
        #pragma unroll
        for (int i = 0; i < 2; i++) {
            size_t r = row0 + wm + i * 16 + (lane >> 2);
            float2 o0 = {acc[i][j][0] + bb.x, acc[i][j][1] + bb.y};
            float2 o1 = {acc[i][j][2] + bb.x, acc[i][j][3] + bb.y};
            *(float2*)&C[r * DMODEL + c]       = o0;
            *(float2*)&C[(r + 8) * DMODEL + c] = o1;
        }
    }
}

// ---------------------------------------------------------------------------
// q+k projections, 3xBF16 split, batched on blockIdx.z. BK=16.
// ---------------------------------------------------------------------------
__global__ __launch_bounds__(256, 2)
void gemm_qk_bf16x3(const float* __restrict__ qin, const float* __restrict__ kin,
                    const float* __restrict__ wq, const float* __restrict__ wk,
                    const float* __restrict__ bq, const float* __restrict__ bk,
                    float* __restrict__ gq, float* __restrict__ gk) {
    const float* A    = blockIdx.z ? kin : qin;
    const float* W    = blockIdx.z ? wk  : wq;
    const float* bias = blockIdx.z ? bk  : bq;
    float* C          = blockIdx.z ? gk  : gq;

    __shared__ unsigned Ah2[8][132], Al2[8][132];
    __shared__ unsigned Bh2[8][132], Bl2[8][132];
    const int tid = threadIdx.x, lane = tid & 31, warp = tid >> 5;
    const int wm = (warp & 3) * 32, wn = (warp >> 2) * 64;
    const int row0 = blockIdx.y * 128, col0 = blockIdx.x * 128;
    const int kq = lane & 3;

    float acc[2][8][4] = {};
    for (int k0 = 0; k0 < DMODEL; k0 += 16) {
        #pragma unroll
        for (int l = 0; l < 2; l++) {
            int idx = tid + l * 256, r = idx >> 2, kc = (idx & 3) << 2;
            int kp = kc >> 1;
            float4 a4 = *(const float4*)&A[(size_t)(row0 + r) * DMODEL + k0 + kc];
            float4 b4 = *(const float4*)&W[(size_t)(col0 + r) * DMODEL + k0 + kc];
            unsigned h0, l0, h1, l1;
            splitbf2(a4.x, a4.y, h0, l0); splitbf2(a4.z, a4.w, h1, l1);
            Ah2[kp][r] = h0; Ah2[kp+1][r] = h1; Al2[kp][r] = l0; Al2[kp+1][r] = l1;
            splitbf2(b4.x, b4.y, h0, l0); splitbf2(b4.z, b4.w, h1, l1);
            Bh2[kp][r] = h0; Bh2[kp+1][r] = h1; Bl2[kp][r] = l0; Bl2[kp+1][r] = l1;
        }
        __syncthreads();
        unsigned ah[2][4], al[2][4];
        #pragma unroll
        for (int i = 0; i < 2; i++) {
            int m0 = wm + i * 16 + (lane >> 2);
            ah[i][0]=Ah2[kq][m0];   ah[i][1]=Ah2[kq][m0+8];
            ah[i][2]=Ah2[kq+4][m0]; ah[i][3]=Ah2[kq+4][m0+8];
            al[i][0]=Al2[kq][m0];   al[i][1]=Al2[kq][m0+8];
            al[i][2]=Al2[kq+4][m0]; al[i][3]=Al2[kq+4][m0+8];
        }
        #pragma unroll
        for (int j = 0; j < 8; j++) {
            int nb = wn + j * 8 + (lane >> 2);
            unsigned bh2[2] = {Bh2[kq][nb], Bh2[kq+4][nb]};
            unsigned bl2[2] = {Bl2[kq][nb], Bl2[kq+4][nb]};
            #pragma unroll
            for (int i = 0; i < 2; i++) {
                mma16(acc[i][j], al[i], bh2);
                mma16(acc[i][j], ah[i], bl2);
                mma16(acc[i][j], ah[i], bh2);
            }
        }
        __syncthreads();
    }
    #pragma unroll
    for (int j = 0; j < 8; j++) {
        int c = col0 + wn + j * 8 + (lane & 3) * 2;
        float2 bb = *(const float2*)&bias[c];
        #pragma unroll
        for (int i = 0; i < 2; i++) {
            size_t r = row0 + wm + i * 16 + (lane >> 2);
            float2 o0 = {acc[i][j][0] + bb.x, acc[i][j][1] + bb.y};
            float2 o1 = {acc[i][j][2] + bb.x, acc[i][j][3] + bb.y};
            *(float2*)&C[r * DMODEL + c]       = o0;
            *(float2*)&C[(r + 8) * DMODEL + c] = o1;
        }
    }
}

// ---------------------------------------------------------------------------
// Fused scores (3xBF16) + mask + exp -> unnormalized P + rowsum partials.
// grid (NKT, 16, 32).
// ---------------------------------------------------------------------------
__global__ __launch_bounds__(256, 2)
void scores_exp(const float* __restrict__ gq, const float* __restrict__ gk,
                const int* __restrict__ mask, float* __restrict__ attn,
                float* __restrict__ partial) {
    __shared__ unsigned Ah2[8][132], Al2[8][132];
    __shared__ unsigned Bh2[8][132], Bl2[8][132];
    __shared__ float sums[2][128];
    const int tid = threadIdx.x, lane = tid & 31, warp = tid >> 5;
    const int wm = (warp & 3) * 32, wn = (warp >> 2) * 64;
    const int bh_i = blockIdx.z, b = bh_i >> 4, h = bh_i & 15;
    const int q0 = blockIdx.y * 128, c0 = blockIdx.x * 128;
    const float* Qb = gq + (size_t)b * SEQ * DMODEL + h * DHEAD;
    const float* Kb = gk + (size_t)b * SEQ * DMODEL + h * DHEAD;
    const int kq = lane & 3;

    float acc[2][8][4] = {};
    #pragma unroll
    for (int k0 = 0; k0 < DHEAD; k0 += 16) {
        #pragma unroll
        for (int l = 0; l < 2; l++) {
            int idx = tid + l * 256, r = idx >> 2, kc = (idx & 3) << 2;
            int kp = kc >> 1;
            float4 a4 = *(const float4*)&Qb[(size_t)(q0 + r) * DMODEL + k0 + kc];
            float4 b4 = *(const float4*)&Kb[(size_t)(c0 + r) * DMODEL + k0 + kc];
            unsigned h0, l0, h1, l1;
            splitbf2(a4.x, a4.y, h0, l0); splitbf2(a4.z, a4.w, h1, l1);
            Ah2[kp][r] = h0; Ah2[kp+1][r] = h1; Al2[kp][r] = l0; Al2[kp+1][r] = l1;
            splitbf2(b4.x, b4.y, h0, l0); splitbf2(b4.z, b4.w, h1, l1);
            Bh2[kp][r] = h0; Bh2[kp+1][r] = h1; Bl2[kp][r] = l0; Bl2[kp+1][r] = l1;
        }
        __syncthreads();
        unsigned ah[2][4], al[2][4];
        #pragma unroll
        for (int i = 0; i < 2; i++) {
            int m0 = wm + i * 16 + (lane >> 2);
            ah[i][0]=Ah2[kq][m0];   ah[i][1]=Ah2[kq][m0+8];
            ah[i][2]=Ah2[kq+4][m0]; ah[i][3]=Ah2[kq+4][m0+8];
            al[i][0]=Al2[kq][m0];   al[i][1]=Al2[kq][m0+8];
            al[i][2]=Al2[kq+4][m0]; al[i][3]=Al2[kq+4][m0+8];
        }
        #pragma unroll
        for (int j = 0; j < 8; j++) {
            int nb = wn + j * 8 + (lane >> 2);
            unsigned bh2[2] = {Bh2[kq][nb], Bh2[kq+4][nb]};
            unsigned bl2[2] = {Bl2[kq][nb], Bl2[kq+4][nb]};
            #pragma unroll
            for (int i = 0; i < 2; i++) {
                mma16(acc[i][j], al[i], bh2);
                mma16(acc[i][j], ah[i], bl2);
                mma16(acc[i][j], ah[i], bh2);
            }
        }
        __syncthreads();
    }

    // Epilogue: mask -> exp (unnormalized) -> write P, accumulate row sums.
    const int* mrow = mask + (size_t)b * SEQ * SEQ;
    float* out = attn + (size_t)bh_i * SEQ * SEQ;
    float rs[2][2] = {};
    #pragma unroll
    for (int j = 0; j < 8; j++) {
        int c = c0 + wn + j * 8 + (lane & 3) * 2;
        #pragma unroll
        for (int i = 0; i < 2; i++) {
            size_t r = q0 + wm + i * 16 + (lane >> 2);
            int2 m0v = *(const int2*)&mrow[r * SEQ + c];
            int2 m1v = *(const int2*)&mrow[(r + 8) * SEQ + c];
            float2 o0, o1;
            o0.x = m0v.x ? __expf(acc[i][j][0] * 0.125f) : 0.f;
            o0.y = m0v.y ? __expf(acc[i][j][1] * 0.125f) : 0.f;
            o1.x = m1v.x ? __expf(acc[i][j][2] * 0.125f) : 0.f;
            o1.y = m1v.y ? __expf(acc[i][j][3] * 0.125f) : 0.f;
            *(float2*)&out[r * SEQ + c]       = o0;
            *(float2*)&out[(r + 8) * SEQ + c] = o1;
            rs[i][0] += o0.x + o0.y;
            rs[i][1] += o1.x + o1.y;
        }
    }
    #pragma unroll
    for (int i = 0; i < 2; i++)
        #pragma unroll
        for (int hh = 0; hh < 2; hh++) {
            float v = rs[i][hh];
            v += __shfl_xor_sync(0xffffffffu, v, 1);
            v += __shfl_xor_sync(0xffffffffu, v, 2);
            if ((lane & 3) == 0)
                sums[warp >> 2][wm + i * 16 + hh * 8 + (lane >> 2)] = v;
        }
    __syncthreads();
    if (tid < 128) {
        float tot = sums[0][tid] + sums[1][tid];
        partial[((size_t)bh_i * SEQ + q0 + tid) * NKT + blockIdx.x] = tot;
    }
}

// ---------------------------------------------------------------------------
// Fused PV (1xTF32, split-K) + normalization. grid (SPLITK, 16, 32).
// Each CTA handles 512 keys; writes normalized P in place (disjoint columns)
// and emits partial ctx to its split buffer.
// ---------------------------------------------------------------------------
__global__ __launch_bounds__(256, 2)
void pv_norm(float* __restrict__ attn, const float* __restrict__ gv,
             const float* __restrict__ partial, float* __restrict__ pctx) {
    __shared__ unsigned Ps[16][136];
    __shared__ unsigned Vs[16][72];
    __shared__ float inv_s[128];
    const int tid = threadIdx.x, lane = tid & 31, warp = tid >> 5;
    const int wm = (warp & 3) * 32, wn = (warp >> 2) * 32;
    const int bh_i = blockIdx.z, b = bh_i >> 4, h = bh_i & 15;
    float* P = attn + (size_t)bh_i * SEQ * SEQ;
    const float* V = gv + (size_t)b * SEQ * DMODEL + h * DHEAD;
    float* Cc = pctx + (size_t)blockIdx.x * MROWS * DMODEL
                     + (size_t)b * SEQ * DMODEL + h * DHEAD;
    const int q0 = blockIdx.y * 128;
    const int kbase = blockIdx.x * (SEQ / SPLITK);

    if (tid < 128) {
        const float4* pp = (const float4*)&partial[((size_t)bh_i * SEQ + q0 + tid) * NKT];
        float4 p0 = pp[0], p1 = pp[1], p2 = pp[2], p3 = pp[3];
        float s = ((p0.x + p0.y) + (p0.z + p0.w)) + ((p1.x + p1.y) + (p1.z + p1.w))
                + ((p2.x + p2.y) + (p2.z + p2.w)) + ((p3.x + p3.y) + (p3.z + p3.w));
        inv_s[tid] = 1.0f / s;
    }
    __syncthreads();

    float acc[2][4][4] = {};
    for (int k0 = kbase; k0 < kbase + SEQ / SPLITK; k0 += 16) {
        #pragma unroll
        for (int l = 0; l < 2; l++) {
            int idx = tid + l * 256, r = idx >> 2, kc = (idx & 3) << 2;
            size_t off = (size_t)(q0 + r) * SEQ + k0 + kc;
            float4 a4 = *(const float4*)&P[off];
            float sc = inv_s[r];
            a4.x *= sc; a4.y *= sc; a4.z *= sc; a4.w *= sc;
            *(float4*)&P[off] = a4;   // normalized attention output
            Ps[kc+0][r]=f2tf(a4.x); Ps[kc+1][r]=f2tf(a4.y);
            Ps[kc+2][r]=f2tf(a4.z); Ps[kc+3][r]=f2tf(a4.w);
        }
        {
            int kk = tid >> 4, c = (tid & 15) << 2;
            float4 b4 = *(const float4*)&V[(size_t)(k0 + kk) * DMODEL + c];
            Vs[kk][c+0]=f2tf(b4.x); Vs[kk][c+1]=f2tf(b4.y);
            Vs[kk][c+2]=f2tf(b4.z); Vs[kk][c+3]=f2tf(b4.w);
        }
        __syncthreads();
        #pragma unroll
        for (int kk = 0; kk < 16; kk += 8) {
            const int kr = kk + (lane & 3), m0 = wm + (lane >> 2);
            unsigned af[2][4];
            #pragma unroll
            for (int i = 0; i < 2; i++) {
                af[i][0]=Ps[kr][m0+i*16];   af[i][1]=Ps[kr][m0+i*16+8];
                af[i][2]=Ps[kr+4][m0+i*16]; af[i][3]=Ps[kr+4][m0+i*16+8];
            }
            #pragma unroll
            for (int j = 0; j < 4; j++) {
                int nb = wn + j * 8 + (lane >> 2);
                unsigned bf[2] = {Vs[kr][nb], Vs[kr+4][nb]};
                mma8(acc[0][j], af[0], bf);
                mma8(acc[1][j], af[1], bf);
            }
        }
        __syncthreads();
    }
    #pragma unroll
    for (int j = 0; j < 4; j++) {
        int c = wn + j * 8 + (lane & 3) * 2;
        #pragma unroll
        for (int i = 0; i < 2; i++) {
            size_t r = q0 + wm + i * 16 + (lane >> 2);
            float2 o0 = {acc[i][j][0], acc[i][j][1]};
            float2 o1 = {acc[i][j][2], acc[i][j][3]};
            *(float2*)&Cc[r * DMODEL + c]       = o0;
            *(float2*)&Cc[(r + 8) * DMODEL + c] = o1;
        }
    }
}

// ---------------------------------------------------------------------------
// Residual + LayerNorm.
// ---------------------------------------------------------------------------
__global__ void ln_kernel(const float* __restrict__ resid,
                          const float* __restrict__ x,
                          const float* __restrict__ gamma,
                          const float* __restrict__ beta,
                          float* __restrict__ out) {
    const size_t row = blockIdx.x;
    const float4* xr = reinterpret_cast<const float4*>(x + row * DMODEL);
    const float4* rr = reinterpret_cast<const float4*>(resid + row * DMODEL);
    const int t = threadIdx.x;
    __shared__ float sred[8];

    float4 a = rr[t], bv = xr[t];
    float4 v = {a.x + bv.x, a.y + bv.y, a.z + bv.z, a.w + bv.w};
    float s = v.x + v.y + v.z + v.w;
    #pragma unroll
    for (int o = 16; o > 0; o >>= 1) s += __shfl_xor_sync(0xffffffffu, s, o);
    if ((t & 31) == 0) sred[t >> 5] = s;
    __syncthreads();
    float tot = 0.f;
    #pragma unroll
    for (int i = 0; i < 8; i++) tot += sred[i];
    const float mu = tot * (1.0f / DMODEL);
    __syncthreads();

    float dx = v.x - mu, dy = v.y - mu, dz = v.z - mu, dw = v.w - mu;
    float sq = dx*dx + dy*dy + dz*dz + dw*dw;
    #pragma unroll
    for (int o = 16; o > 0; o >>= 1) sq += __shfl_xor_sync(0xffffffffu, sq, o);
    if ((t & 31) == 0) sred[t >> 5] = sq;
    __syncthreads();
    float tot2 = 0.f;
    #pragma unroll
    for (int i = 0; i < 8; i++) tot2 += sred[i];
    const float inv = rsqrtf(tot2 * (1.0f / DMODEL) + 1e-5f);

    float4 g = reinterpret_cast<const float4*>(gamma)[t];
    float4 be = reinterpret_cast<const float4*>(beta)[t];
    float4 o;
    o.x = dx * inv * g.x + be.x;
    o.y = dy * inv * g.y + be.y;
    o.z = dz * inv * g.z + be.z;
    o.w = dw * inv * g.w + be.w;
    reinterpret_cast<float4*>(out + row * DMODEL)[t] = o;
}

// ---------------------------------------------------------------------------
extern "C" void kernel_launch(void* const* d_in, const int* in_sizes, int n_in,
                              void* d_out, int out_size) {
    const float* q     = (const float*)d_in[0];
    const float* k     = (const float*)d_in[1];
    const float* v     = (const float*)d_in[2];
    const int*   mask  = (const int*)  d_in[3];
    const float* wq    = (const float*)d_in[4];
    const float* bq    = (const float*)d_in[5];
    const float* wk    = (const float*)d_in[6];
    const float* bk    = (const float*)d_in[7];
    const float* wv    = (const float*)d_in[8];
    const float* bv    = (const float*)d_in[9];
    const float* wo    = (const float*)d_in[10];
    const float* bo    = (const float*)d_in[11];
    const float* gamma = (const float*)d_in[12];
    const float* beta  = (const float*)d_in[13];

    float* out  = (float*)d_out;
    float* attn = out + ATT_OFF;

    void* sp = nullptr;
    cudaGetSymbolAddress(&sp, g_scratch);
    const size_t PS = (size_t)MROWS * DMODEL;
    float* gq      = (float*)sp;
    float* gk      = gq + PS;
    float* gv      = gk + PS;
    float* go      = gv + PS;
    float* pctx    = go + PS;            // 4 x PS
    float* partial = pctx + 4 * PS;

    dim3 gQK(DMODEL / 128, MROWS / 128, 2);             // (8, 32, 2)
    gemm_qk_bf16x3<<<gQK, 256>>>(q, k, wq, wk, bq, bk, gq, gk);

    dim3 gProj(DMODEL / 128, MROWS / 128);              // (8, 32)
    gemm_nt_tf32<<<gProj, 256>>>(v, wv, bv, gv);

    dim3 gScores(NKT, SEQ / 128, BATCH * NHEADS);       // (16, 16, 32)
    scores_exp<<<gScores, 256>>>(gq, gk, mask, attn, partial);

    dim3 gPV(SPLITK, SEQ / 128, BATCH * NHEADS);        // (4, 16, 32)
    pv_norm<<<gPV, 256>>>(attn, gv, partial, pctx);

    gemm_o_tf32<<<gProj, 256>>>(pctx, wo, bo, go);

    ln_kernel<<<MROWS, 256>>>(q, go, gamma, beta, out);
}

// round 6
// speedup vs baseline: 2.6994x; 1.1335x over previous
#include <cuda_runtime.h>
#include <cuda_bf16.h>
#include <math.h>

#define BATCH 2
#define SEQ   2048
#define DMODEL 1024
#define NHEADS 16
#define DHEAD  64
#define MROWS (BATCH*SEQ)                    // 4096
#define ATT_OFF ((size_t)BATCH*SEQ*DMODEL)
#define NKT 16                               // key tiles in scores grid
#define SPLITK 2                             // pv split-K factor

// gq, gk, gv, go (4 x PS) + pctx (2 x PS) + rowsum partials
__device__ float g_scratch[6ull * MROWS * DMODEL + (size_t)BATCH * NHEADS * SEQ * NKT];

// scores_exp dynamic smem: 4 strip arrays [32][132] u32 + sums [2][128]
#define SC_SMEM (4 * 32 * 132 * 4 + 2 * 128 * 4)

// ---------------------------------------------------------------------------
__device__ __forceinline__ unsigned f2tf(float x) {
    unsigned r;
    asm("cvt.rna.tf32.f32 %0, %1;" : "=r"(r) : "f"(x));
    return r;
}
__device__ __forceinline__ void mma8(float* d, const unsigned* a, const unsigned* b) {
    asm volatile(
        "mma.sync.aligned.m16n8k8.row.col.f32.tf32.tf32.f32 "
        "{%0,%1,%2,%3}, {%4,%5,%6,%7}, {%8,%9}, {%0,%1,%2,%3};"
        : "+f"(d[0]), "+f"(d[1]), "+f"(d[2]), "+f"(d[3])
        : "r"(a[0]), "r"(a[1]), "r"(a[2]), "r"(a[3]), "r"(b[0]), "r"(b[1]));
}
__device__ __forceinline__ void mma16(float* d, const unsigned* a, const unsigned* b) {
    asm volatile(
        "mma.sync.aligned.m16n8k16.row.col.f32.bf16.bf16.f32 "
        "{%0,%1,%2,%3}, {%4,%5,%6,%7}, {%8,%9}, {%0,%1,%2,%3};"
        : "+f"(d[0]), "+f"(d[1]), "+f"(d[2]), "+f"(d[3])
        : "r"(a[0]), "r"(a[1]), "r"(a[2]), "r"(a[3]), "r"(b[0]), "r"(b[1]));
}
__device__ __forceinline__ void splitbf2(float x, float y, unsigned& hi, unsigned& lo) {
    __nv_bfloat16 hx = __float2bfloat16_rn(x);
    __nv_bfloat16 hy = __float2bfloat16_rn(y);
    __nv_bfloat16 lx = __float2bfloat16_rn(x - __bfloat162float(hx));
    __nv_bfloat16 ly = __float2bfloat16_rn(y - __bfloat162float(hy));
    hi = (unsigned)__bfloat16_as_ushort(hx) | ((unsigned)__bfloat16_as_ushort(hy) << 16);
    lo = (unsigned)__bfloat16_as_ushort(lx) | ((unsigned)__bfloat16_as_ushort(ly) << 16);
}

// ---------------------------------------------------------------------------
// 1x TF32 NT GEMM + bias (v projection), software pipelined.
// block 128x128, BK=16, 256 thr, warps 4(M)x2(N).
// ---------------------------------------------------------------------------
__global__ __launch_bounds__(256, 2)
void gemm_nt_tf32(const float* __restrict__ A, const float* __restrict__ W,
                  const float* __restrict__ bias, float* __restrict__ C) {
    __shared__ unsigned As[2][16][136];
    __shared__ unsigned Bs[2][16][136];
    const int tid = threadIdx.x, lane = tid & 31, warp = tid >> 5;
    const int wm = (warp & 3) * 32, wn = (warp >> 2) * 64;
    const int row0 = blockIdx.y * 128, col0 = blockIdx.x * 128;

    float4 ra[2], rb[2];
    auto doload = [&](int k0) {
        #pragma unroll
        for (int l = 0; l < 2; l++) {
            int idx = tid + l * 256, r = idx >> 2, kc = (idx & 3) << 2;
            ra[l] = *(const float4*)&A[(size_t)(row0 + r) * DMODEL + k0 + kc];
            rb[l] = *(const float4*)&W[(size_t)(col0 + r) * DMODEL + k0 + kc];
        }
    };
    auto dostore = [&](int bf) {
        #pragma unroll
        for (int l = 0; l < 2; l++) {
            int idx = tid + l * 256, r = idx >> 2, kc = (idx & 3) << 2;
            As[bf][kc+0][r]=f2tf(ra[l].x); As[bf][kc+1][r]=f2tf(ra[l].y);
            As[bf][kc+2][r]=f2tf(ra[l].z); As[bf][kc+3][r]=f2tf(ra[l].w);
            Bs[bf][kc+0][r]=f2tf(rb[l].x); Bs[bf][kc+1][r]=f2tf(rb[l].y);
            Bs[bf][kc+2][r]=f2tf(rb[l].z); Bs[bf][kc+3][r]=f2tf(rb[l].w);
        }
    };

    float acc[2][8][4] = {};
    doload(0); dostore(0); __syncthreads();
    int bf = 0;
    for (int k0 = 0; k0 < DMODEL; k0 += 16) {
        bool more = (k0 + 16 < DMODEL);
        if (more) doload(k0 + 16);
        #pragma unroll
        for (int kk = 0; kk < 16; kk += 8) {
            const int kr = kk + (lane & 3), m0 = wm + (lane >> 2);
            unsigned af[2][4];
            #pragma unroll
            for (int i = 0; i < 2; i++) {
                af[i][0] = As[bf][kr][m0 + i*16];     af[i][1] = As[bf][kr][m0 + i*16 + 8];
                af[i][2] = As[bf][kr+4][m0 + i*16];   af[i][3] = As[bf][kr+4][m0 + i*16 + 8];
            }
            #pragma unroll
            for (int j = 0; j < 8; j++) {
                int nb = wn + j * 8 + (lane >> 2);
                unsigned bfr[2] = {Bs[bf][kr][nb], Bs[bf][kr+4][nb]};
                mma8(acc[0][j], af[0], bfr);
                mma8(acc[1][j], af[1], bfr);
            }
        }
        if (more) { dostore(bf ^ 1); __syncthreads(); bf ^= 1; }
    }
    #pragma unroll
    for (int j = 0; j < 8; j++) {
        int c = col0 + wn + j * 8 + (lane & 3) * 2;
        float2 bb = *(const float2*)&bias[c];
        #pragma unroll
        for (int i = 0; i < 2; i++) {
            size_t r = row0 + wm + i * 16 + (lane >> 2);
            float2 o0 = {acc[i][j][0] + bb.x, acc[i][j][1] + bb.y};
            float2 o1 = {acc[i][j][2] + bb.x, acc[i][j][3] + bb.y};
            *(float2*)&C[r * DMODEL + c]       = o0;
            *(float2*)&C[(r + 8) * DMODEL + c] = o1;
        }
    }
}

// ---------------------------------------------------------------------------
// O projection: A = sum of SPLITK partial ctx buffers, pipelined.
// ---------------------------------------------------------------------------
__global__ __launch_bounds__(256, 2)
void gemm_o_tf32(const float* __restrict__ pctx, const float* __restrict__ W,
                 const float* __restrict__ bias, float* __restrict__ C) {
    __shared__ unsigned As[2][16][136];
    __shared__ unsigned Bs[2][16][136];
    const int tid = threadIdx.x, lane = tid & 31, warp = tid >> 5;
    const int wm = (warp & 3) * 32, wn = (warp >> 2) * 64;
    const int row0 = blockIdx.y * 128, col0 = blockIdx.x * 128;
    const size_t PS = (size_t)MROWS * DMODEL;

    float4 ra0[2], ra1[2], rb[2];
    auto doload = [&](int k0) {
        #pragma unroll
        for (int l = 0; l < 2; l++) {
            int idx = tid + l * 256, r = idx >> 2, kc = (idx & 3) << 2;
            size_t off = (size_t)(row0 + r) * DMODEL + k0 + kc;
            ra0[l] = *(const float4*)&pctx[off];
            ra1[l] = *(const float4*)&pctx[off + PS];
            rb[l]  = *(const float4*)&W[(size_t)(col0 + r) * DMODEL + k0 + kc];
        }
    };
    auto dostore = [&](int bf) {
        #pragma unroll
        for (int l = 0; l < 2; l++) {
            int idx = tid + l * 256, r = idx >> 2, kc = (idx & 3) << 2;
            float4 a4 = {ra0[l].x + ra1[l].x, ra0[l].y + ra1[l].y,
                         ra0[l].z + ra1[l].z, ra0[l].w + ra1[l].w};
            As[bf][kc+0][r]=f2tf(a4.x); As[bf][kc+1][r]=f2tf(a4.y);
            As[bf][kc+2][r]=f2tf(a4.z); As[bf][kc+3][r]=f2tf(a4.w);
            Bs[bf][kc+0][r]=f2tf(rb[l].x); Bs[bf][kc+1][r]=f2tf(rb[l].y);
            Bs[bf][kc+2][r]=f2tf(rb[l].z); Bs[bf][kc+3][r]=f2tf(rb[l].w);
        }
    };

    float acc[2][8][4] = {};
    doload(0); dostore(0); __syncthreads();
    int bf = 0;
    for (int k0 = 0; k0 < DMODEL; k0 += 16) {
        bool more = (k0 + 16 < DMODEL);
        if (more) doload(k0 + 16);
        #pragma unroll
        for (int kk = 0; kk < 16; kk += 8) {
            const int kr = kk + (lane & 3), m0 = wm + (lane >> 2);
            unsigned af[2][4];
            #pragma unroll
            for (int i = 0; i < 2; i++) {
                af[i][0] = As[bf][kr][m0 + i*16];     af[i][1] = As[bf][kr][m0 + i*16 + 8];
                af[i][2] = As[bf][kr+4][m0 + i*16];   af[i][3] = As[bf][kr+4][m0 + i*16 + 8];
            }
            #pragma unroll
            for (int j = 0; j < 8; j++) {
                int nb = wn + j * 8 + (lane >> 2);
                unsigned bfr[2] = {Bs[bf][kr][nb], Bs[bf][kr+4][nb]};
                mma8(acc[0][j], af[0], bfr);
                mma8(acc[1][j], af[1], bfr);
            }
        }
        if (more) { dostore(bf ^ 1); __syncthreads(); bf ^= 1; }
    }
    #pragma unroll
    for (int j = 0; j < 8; j++) {
        int c = col0 + wn + j * 8 + (lane & 3) * 2;
        float2 bb = *(const float2*)&bias[c];
        #pragma unroll
        for (int i = 0; i < 2; i++) {
            size_t r = row0 + wm + i * 16 + (lane >> 2);
            float2 o0 = {acc[i][j][0] + bb.x, acc[i][j][1] + bb.y};
            float2 o1 = {acc[i][j][2] + bb.x, acc[i][j][3] + bb.y};
            *(float2*)&C[r * DMODEL + c]       = o0;
            *(float2*)&C[(r + 8) * DMODEL + c] = o1;
        }
    }
}

// ---------------------------------------------------------------------------
// q+k projections, 3xBF16 split, pipelined, batched on blockIdx.z.
// ---------------------------------------------------------------------------
__global__ __launch_bounds__(256, 2)
void gemm_qk_bf16x3(const float* __restrict__ qin, const float* __restrict__ kin,
                    const float* __restrict__ wq, const float* __restrict__ wk,
                    const float* __restrict__ bq, const float* __restrict__ bk,
                    float* __restrict__ gq, float* __restrict__ gk) {
    const float* A    = blockIdx.z ? kin : qin;
    const float* W    = blockIdx.z ? wk  : wq;
    const float* bias = blockIdx.z ? bk  : bq;
    float* C          = blockIdx.z ? gk  : gq;

    __shared__ unsigned Ah2[2][8][132], Al2[2][8][132];
    __shared__ unsigned Bh2[2][8][132], Bl2[2][8][132];
    const int tid = threadIdx.x, lane = tid & 31, warp = tid >> 5;
    const int wm = (warp & 3) * 32, wn = (warp >> 2) * 64;
    const int row0 = blockIdx.y * 128, col0 = blockIdx.x * 128;
    const int kq = lane & 3;

    float4 ra[2], rb[2];
    auto doload = [&](int k0) {
        #pragma unroll
        for (int l = 0; l < 2; l++) {
            int idx = tid + l * 256, r = idx >> 2, kc = (idx & 3) << 2;
            ra[l] = *(const float4*)&A[(size_t)(row0 + r) * DMODEL + k0 + kc];
            rb[l] = *(const float4*)&W[(size_t)(col0 + r) * DMODEL + k0 + kc];
        }
    };
    auto dostore = [&](int bf) {
        #pragma unroll
        for (int l = 0; l < 2; l++) {
            int idx = tid + l * 256, r = idx >> 2, kc = (idx & 3) << 2, kp = kc >> 1;
            unsigned h0, l0, h1, l1;
            splitbf2(ra[l].x, ra[l].y, h0, l0); splitbf2(ra[l].z, ra[l].w, h1, l1);
            Ah2[bf][kp][r] = h0; Ah2[bf][kp+1][r] = h1;
            Al2[bf][kp][r] = l0; Al2[bf][kp+1][r] = l1;
            splitbf2(rb[l].x, rb[l].y, h0, l0); splitbf2(rb[l].z, rb[l].w, h1, l1);
            Bh2[bf][kp][r] = h0; Bh2[bf][kp+1][r] = h1;
            Bl2[bf][kp][r] = l0; Bl2[bf][kp+1][r] = l1;
        }
    };

    float acc[2][8][4] = {};
    doload(0); dostore(0); __syncthreads();
    int bf = 0;
    for (int k0 = 0; k0 < DMODEL; k0 += 16) {
        bool more = (k0 + 16 < DMODEL);
        if (more) doload(k0 + 16);
        unsigned ah[2][4], al[2][4];
        #pragma unroll
        for (int i = 0; i < 2; i++) {
            int m0 = wm + i * 16 + (lane >> 2);
            ah[i][0]=Ah2[bf][kq][m0];   ah[i][1]=Ah2[bf][kq][m0+8];
            ah[i][2]=Ah2[bf][kq+4][m0]; ah[i][3]=Ah2[bf][kq+4][m0+8];
            al[i][0]=Al2[bf][kq][m0];   al[i][1]=Al2[bf][kq][m0+8];
            al[i][2]=Al2[bf][kq+4][m0]; al[i][3]=Al2[bf][kq+4][m0+8];
        }
        #pragma unroll
        for (int j = 0; j < 8; j++) {
            int nb = wn + j * 8 + (lane >> 2);
            unsigned bh2[2] = {Bh2[bf][kq][nb], Bh2[bf][kq+4][nb]};
            unsigned bl2[2] = {Bl2[bf][kq][nb], Bl2[bf][kq+4][nb]};
            #pragma unroll
            for (int i = 0; i < 2; i++) {
                mma16(acc[i][j], al[i], bh2);
                mma16(acc[i][j], ah[i], bl2);
                mma16(acc[i][j], ah[i], bh2);
            }
        }
        if (more) { dostore(bf ^ 1); __syncthreads(); bf ^= 1; }
    }
    #pragma unroll
    for (int j = 0; j < 8; j++) {
        int c = col0 + wn + j * 8 + (lane & 3) * 2;
        float2 bb = *(const float2*)&bias[c];
        #pragma unroll
        for (int i = 0; i < 2; i++) {
            size_t r = row0 + wm + i * 16 + (lane >> 2);
            float2 o0 = {acc[i][j][0] + bb.x, acc[i][j][1] + bb.y};
            float2 o1 = {acc[i][j][2] + bb.x, acc[i][j][3] + bb.y};
            *(float2*)&C[r * DMODEL + c]       = o0;
            *(float2*)&C[(r + 8) * DMODEL + c] = o1;
        }
    }
}

// ---------------------------------------------------------------------------
// Fused scores (3xBF16) + mask + exp -> unnormalized P + rowsum partials.
// Full Q/K strips (DHEAD=64) loaded once into dynamic smem; one sync; 4 MMA
// iterations; epilogue. grid (NKT, 16, 32).
// ---------------------------------------------------------------------------
__global__ __launch_bounds__(256, 2)
void scores_exp(const float* __restrict__ gq, const float* __restrict__ gk,
                const int* __restrict__ mask, float* __restrict__ attn,
                float* __restrict__ partial) {
    extern __shared__ unsigned dsm[];
    unsigned (*Ah2)[132] = (unsigned(*)[132])dsm;        // [32][132]
    unsigned (*Al2)[132] = Ah2 + 32;
    unsigned (*Bh2)[132] = Al2 + 32;
    unsigned (*Bl2)[132] = Bh2 + 32;
    float* sums = (float*)(Bl2 + 32);                    // [2][128]

    const int tid = threadIdx.x, lane = tid & 31, warp = tid >> 5;
    const int wm = (warp & 3) * 32, wn = (warp >> 2) * 64;
    const int bh_i = blockIdx.z, b = bh_i >> 4, h = bh_i & 15;
    const int q0 = blockIdx.y * 128, c0 = blockIdx.x * 128;
    const float* Qb = gq + (size_t)b * SEQ * DMODEL + h * DHEAD;
    const float* Kb = gk + (size_t)b * SEQ * DMODEL + h * DHEAD;
    const int kq = lane & 3;

    // Load full 128x64 strips of Q and K (8 float4 each per thread).
    #pragma unroll
    for (int l = 0; l < 8; l++) {
        int idx = tid + l * 256, r = idx >> 4, kc = (idx & 15) << 2, kp = kc >> 1;
        float4 a4 = *(const float4*)&Qb[(size_t)(q0 + r) * DMODEL + kc];
        float4 b4 = *(const float4*)&Kb[(size_t)(c0 + r) * DMODEL + kc];
        unsigned h0, l0, h1, l1;
        splitbf2(a4.x, a4.y, h0, l0); splitbf2(a4.z, a4.w, h1, l1);
        Ah2[kp][r] = h0; Ah2[kp+1][r] = h1; Al2[kp][r] = l0; Al2[kp+1][r] = l1;
        splitbf2(b4.x, b4.y, h0, l0); splitbf2(b4.z, b4.w, h1, l1);
        Bh2[kp][r] = h0; Bh2[kp+1][r] = h1; Bl2[kp][r] = l0; Bl2[kp+1][r] = l1;
    }
    __syncthreads();

    float acc[2][8][4] = {};
    #pragma unroll
    for (int kk = 0; kk < 32; kk += 8) {
        unsigned ah[2][4], al[2][4];
        #pragma unroll
        for (int i = 0; i < 2; i++) {
            int m0 = wm + i * 16 + (lane >> 2);
            ah[i][0]=Ah2[kk+kq][m0];   ah[i][1]=Ah2[kk+kq][m0+8];
            ah[i][2]=Ah2[kk+kq+4][m0]; ah[i][3]=Ah2[kk+kq+4][m0+8];
            al[i][0]=Al2[kk+kq][m0];   al[i][1]=Al2[kk+kq][m0+8];
            al[i][2]=Al2[kk+kq+4][m0]; al[i][3]=Al2[kk+kq+4][m0+8];
        }
        #pragma unroll
        for (int j = 0; j < 8; j++) {
            int nb = wn + j * 8 + (lane >> 2);
            unsigned bh2[2] = {Bh2[kk+kq][nb], Bh2[kk+kq+4][nb]};
            unsigned bl2[2] = {Bl2[kk+kq][nb], Bl2[kk+kq+4][nb]};
            #pragma unroll
            for (int i = 0; i < 2; i++) {
                mma16(acc[i][j], al[i], bh2);
                mma16(acc[i][j], ah[i], bl2);
                mma16(acc[i][j], ah[i], bh2);
            }
        }
    }

    // Epilogue: mask -> exp (unnormalized) -> write P, accumulate row sums.
    const int* mrow = mask + (size_t)b * SEQ * SEQ;
    float* out = attn + (size_t)bh_i * SEQ * SEQ;
    float rs[2][2] = {};
    #pragma unroll
    for (int j = 0; j < 8; j++) {
        int c = c0 + wn + j * 8 + (lane & 3) * 2;
        #pragma unroll
        for (int i = 0; i < 2; i++) {
            size_t r = q0 + wm + i * 16 + (lane >> 2);
            int2 m0v = *(const int2*)&mrow[r * SEQ + c];
            int2 m1v = *(const int2*)&mrow[(r + 8) * SEQ + c];
            float2 o0, o1;
            o0.x = m0v.x ? __expf(acc[i][j][0] * 0.125f) : 0.f;
            o0.y = m0v.y ? __expf(acc[i][j][1] * 0.125f) : 0.f;
            o1.x = m1v.x ? __expf(acc[i][j][2] * 0.125f) : 0.f;
            o1.y = m1v.y ? __expf(acc[i][j][3] * 0.125f) : 0.f;
            *(float2*)&out[r * SEQ + c]       = o0;
            *(float2*)&out[(r + 8) * SEQ + c] = o1;
            rs[i][0] += o0.x + o0.y;
            rs[i][1] += o1.x + o1.y;
        }
    }
    #pragma unroll
    for (int i = 0; i < 2; i++)
        #pragma unroll
        for (int hh = 0; hh < 2; hh++) {
            float v = rs[i][hh];
            v += __shfl_xor_sync(0xffffffffu, v, 1);
            v += __shfl_xor_sync(0xffffffffu, v, 2);
            if ((lane & 3) == 0)
                sums[(warp >> 2) * 128 + wm + i * 16 + hh * 8 + (lane >> 2)] = v;
        }
    __syncthreads();
    if (tid < 128) {
        float tot = sums[tid] + sums[128 + tid];
        partial[((size_t)bh_i * SEQ + q0 + tid) * NKT + blockIdx.x] = tot;
    }
}

// ---------------------------------------------------------------------------
// Fused PV (1xTF32, split-K=2) + in-place normalization, pipelined.
// grid (SPLITK, 16, 32).
// ---------------------------------------------------------------------------
__global__ __launch_bounds__(256, 2)
void pv_norm(float* __restrict__ attn, const float* __restrict__ gv,
             const float* __restrict__ partial, float* __restrict__ pctx) {
    __shared__ unsigned Ps[2][16][136];
    __shared__ unsigned Vs[2][16][72];
    __shared__ float inv_s[128];
    const int tid = threadIdx.x, lane = tid & 31, warp = tid >> 5;
    const int wm = (warp & 3) * 32, wn = (warp >> 2) * 32;
    const int bh_i = blockIdx.z, b = bh_i >> 4, h = bh_i & 15;
    float* P = attn + (size_t)bh_i * SEQ * SEQ;
    const float* V = gv + (size_t)b * SEQ * DMODEL + h * DHEAD;
    float* Cc = pctx + (size_t)blockIdx.x * MROWS * DMODEL
                     + (size_t)b * SEQ * DMODEL + h * DHEAD;
    const int q0 = blockIdx.y * 128;
    const int kbase = blockIdx.x * (SEQ / SPLITK);
    const int kend  = kbase + SEQ / SPLITK;

    if (tid < 128) {
        const float4* pp = (const float4*)&partial[((size_t)bh_i * SEQ + q0 + tid) * NKT];
        float4 p0 = pp[0], p1 = pp[1], p2 = pp[2], p3 = pp[3];
        float s = ((p0.x + p0.y) + (p0.z + p0.w)) + ((p1.x + p1.y) + (p1.z + p1.w))
                + ((p2.x + p2.y) + (p2.z + p2.w)) + ((p3.x + p3.y) + (p3.z + p3.w));
        inv_s[tid] = 1.0f / s;
    }
    __syncthreads();

    float4 pf[2], vf;
    auto doload = [&](int k0) {
        #pragma unroll
        for (int l = 0; l < 2; l++) {
            int idx = tid + l * 256, r = idx >> 2, kc = (idx & 3) << 2;
            pf[l] = *(const float4*)&P[(size_t)(q0 + r) * SEQ + k0 + kc];
        }
        int kk = tid >> 4, c = (tid & 15) << 2;
        vf = *(const float4*)&V[(size_t)(k0 + kk) * DMODEL + c];
    };
    auto dostore = [&](int bf, int k0) {
        #pragma unroll
        for (int l = 0; l < 2; l++) {
            int idx = tid + l * 256, r = idx >> 2, kc = (idx & 3) << 2;
            float sc = inv_s[r];
            float4 a4 = pf[l];
            a4.x *= sc; a4.y *= sc; a4.z *= sc; a4.w *= sc;
            *(float4*)&P[(size_t)(q0 + r) * SEQ + k0 + kc] = a4;  // normalized out
            Ps[bf][kc+0][r]=f2tf(a4.x); Ps[bf][kc+1][r]=f2tf(a4.y);
            Ps[bf][kc+2][r]=f2tf(a4.z); Ps[bf][kc+3][r]=f2tf(a4.w);
        }
        int kk = tid >> 4, c = (tid & 15) << 2;
        Vs[bf][kk][c+0]=f2tf(vf.x); Vs[bf][kk][c+1]=f2tf(vf.y);
        Vs[bf][kk][c+2]=f2tf(vf.z); Vs[bf][kk][c+3]=f2tf(vf.w);
    };

    float acc[2][4][4] = {};
    doload(kbase); dostore(0, kbase); __syncthreads();
    int bf = 0;
    for (int k0 = kbase; k0 < kend; k0 += 16) {
        bool more = (k0 + 16 < kend);
        if (more) doload(k0 + 16);
        #pragma unroll
        for (int kk = 0; kk < 16; kk += 8) {
            const int kr = kk + (lane & 3), m0 = wm + (lane >> 2);
            unsigned af[2][4];
            #pragma unroll
            for (int i = 0; i < 2; i++) {
                af[i][0]=Ps[bf][kr][m0+i*16];   af[i][1]=Ps[bf][kr][m0+i*16+8];
                af[i][2]=Ps[bf][kr+4][m0+i*16]; af[i][3]=Ps[bf][kr+4][m0+i*16+8];
            }
            #pragma unroll
            for (int j = 0; j < 4; j++) {
                int nb = wn + j * 8 + (lane >> 2);
                unsigned bfr[2] = {Vs[bf][kr][nb], Vs[bf][kr+4][nb]};
                mma8(acc[0][j], af[0], bfr);
                mma8(acc[1][j], af[1], bfr);
            }
        }
        if (more) { dostore(bf ^ 1, k0 + 16); __syncthreads(); bf ^= 1; }
    }
    #pragma unroll
    for (int j = 0; j < 4; j++) {
        int c = wn + j * 8 + (lane & 3) * 2;
        #pragma unroll
        for (int i = 0; i < 2; i++) {
            size_t r = q0 + wm + i * 16 + (lane >> 2);
            float2 o0 = {acc[i][j][0], acc[i][j][1]};
            float2 o1 = {acc[i][j][2], acc[i][j][3]};
            *(float2*)&Cc[r * DMODEL + c]       = o0;
            *(float2*)&Cc[(r + 8) * DMODEL + c] = o1;
        }
    }
}

// ---------------------------------------------------------------------------
// Residual + LayerNorm.
// ---------------------------------------------------------------------------
__global__ void ln_kernel(const float* __restrict__ resid,
                          const float* __restrict__ x,
                          const float* __restrict__ gamma,
                          const float* __restrict__ beta,
                          float* __restrict__ out) {
    const size_t row = blockIdx.x;
    const float4* xr = reinterpret_cast<const float4*>(x + row * DMODEL);
    const float4* rr = reinterpret_cast<const float4*>(resid + row * DMODEL);
    const int t = threadIdx.x;
    __shared__ float sred[8];

    float4 a = rr[t], bv = xr[t];
    float4 v = {a.x + bv.x, a.y + bv.y, a.z + bv.z, a.w + bv.w};
    float s = v.x + v.y + v.z + v.w;
    #pragma unroll
    for (int o = 16; o > 0; o >>= 1) s += __shfl_xor_sync(0xffffffffu, s, o);
    if ((t & 31) == 0) sred[t >> 5] = s;
    __syncthreads();
    float tot = 0.f;
    #pragma unroll
    for (int i = 0; i < 8; i++) tot += sred[i];
    const float mu = tot * (1.0f / DMODEL);
    __syncthreads();

    float dx = v.x - mu, dy = v.y - mu, dz = v.z - mu, dw = v.w - mu;
    float sq = dx*dx + dy*dy + dz*dz + dw*dw;
    #pragma unroll
    for (int o = 16; o > 0; o >>= 1) sq += __shfl_xor_sync(0xffffffffu, sq, o);
    if ((t & 31) == 0) sred[t >> 5] = sq;
    __syncthreads();
    float tot2 = 0.f;
    #pragma unroll
    for (int i = 0; i < 8; i++) tot2 += sred[i];
    const float inv = rsqrtf(tot2 * (1.0f / DMODEL) + 1e-5f);

    float4 g = reinterpret_cast<const float4*>(gamma)[t];
    float4 be = reinterpret_cast<const float4*>(beta)[t];
    float4 o;
    o.x = dx * inv * g.x + be.x;
    o.y = dy * inv * g.y + be.y;
    o.z = dz * inv * g.z + be.z;
    o.w = dw * inv * g.w + be.w;
    reinterpret_cast<float4*>(out + row * DMODEL)[t] = o;
}

// ---------------------------------------------------------------------------
extern "C" void kernel_launch(void* const* d_in, const int* in_sizes, int n_in,
                              void* d_out, int out_size) {
    const float* q     = (const float*)d_in[0];
    const float* k     = (const float*)d_in[1];
    const float* v     = (const float*)d_in[2];
    const int*   mask  = (const int*)  d_in[3];
    const float* wq    = (const float*)d_in[4];
    const float* bq    = (const float*)d_in[5];
    const float* wk    = (const float*)d_in[6];
    const float* bk    = (const float*)d_in[7];
    const float* wv    = (const float*)d_in[8];
    const float* bv    = (const float*)d_in[9];
    const float* wo    = (const float*)d_in[10];
    const float* bo    = (const float*)d_in[11];
    const float* gamma = (const float*)d_in[12];
    const float* beta  = (const float*)d_in[13];

    float* out  = (float*)d_out;
    float* attn = out + ATT_OFF;

    void* sp = nullptr;
    cudaGetSymbolAddress(&sp, g_scratch);
    const size_t PS = (size_t)MROWS * DMODEL;
    float* gq      = (float*)sp;
    float* gk      = gq + PS;
    float* gv      = gk + PS;
    float* go      = gv + PS;
    float* pctx    = go + PS;            // SPLITK x PS
    float* partial = pctx + SPLITK * PS;

    cudaFuncSetAttribute(scores_exp, cudaFuncAttributeMaxDynamicSharedMemorySize, SC_SMEM);

    dim3 gQK(DMODEL / 128, MROWS / 128, 2);             // (8, 32, 2)
    gemm_qk_bf16x3<<<gQK, 256>>>(q, k, wq, wk, bq, bk, gq, gk);

    dim3 gProj(DMODEL / 128, MROWS / 128);              // (8, 32)
    gemm_nt_tf32<<<gProj, 256>>>(v, wv, bv, gv);

    dim3 gScores(NKT, SEQ / 128, BATCH * NHEADS);       // (16, 16, 32)
    scores_exp<<<gScores, 256, SC_SMEM>>>(gq, gk, mask, attn, partial);

    dim3 gPV(SPLITK, SEQ / 128, BATCH * NHEADS);        // (2, 16, 32)
    pv_norm<<<gPV, 256>>>(attn, gv, partial, pctx);

    gemm_o_tf32<<<gProj, 256>>>(pctx, wo, bo, go);

    ln_kernel<<<MROWS, 256>>>(q, go, gamma, beta, out);
}

// round 7
// speedup vs baseline: 3.0587x; 1.1331x over previous
#include <cuda_runtime.h>
#include <cuda_bf16.h>
#include <math.h>

#define BATCH 2
#define SEQ   2048
#define DMODEL 1024
#define NHEADS 16
#define DHEAD  64
#define MROWS (BATCH*SEQ)                    // 4096
#define ATT_OFF ((size_t)BATCH*SEQ*DMODEL)
#define NKT 16                               // key tiles in scores grid
#define SPLITK 2                             // pv split-K factor
#define PVSTG 4
#define VPSTG 4

// gq, gk, gv, go (4 x PS) + pctx (2 x PS) + rowsum partials
__device__ float g_scratch[6ull * MROWS * DMODEL + (size_t)BATCH * NHEADS * SEQ * NKT];

// scores_exp dynamic smem: 4 strip arrays [32][132] u32 + sums [2][128]
#define SC_SMEM (4 * 32 * 132 * 4 + 2 * 128 * 4)
// pv dynamic smem: P stages [4][128][20] + V stages [4][16][72] + inv_s[128]
#define PV_PS   (PVSTG * 128 * 20)
#define PV_VS   (PVSTG * 16 * 72)
#define PV_SMEM ((PV_PS + PV_VS + 128) * 4)
// vproj dynamic smem: A + W stages [4][128][20] each
#define VP_AS   (VPSTG * 128 * 20)
#define VP_SMEM (2 * VP_AS * 4)

// ---------------------------------------------------------------------------
__device__ __forceinline__ unsigned f2tf(float x) {
    unsigned r;
    asm("cvt.rna.tf32.f32 %0, %1;" : "=r"(r) : "f"(x));
    return r;
}
__device__ __forceinline__ void mma8(float* d, const unsigned* a, const unsigned* b) {
    asm volatile(
        "mma.sync.aligned.m16n8k8.row.col.f32.tf32.tf32.f32 "
        "{%0,%1,%2,%3}, {%4,%5,%6,%7}, {%8,%9}, {%0,%1,%2,%3};"
        : "+f"(d[0]), "+f"(d[1]), "+f"(d[2]), "+f"(d[3])
        : "r"(a[0]), "r"(a[1]), "r"(a[2]), "r"(a[3]), "r"(b[0]), "r"(b[1]));
}
__device__ __forceinline__ void mma16(float* d, const unsigned* a, const unsigned* b) {
    asm volatile(
        "mma.sync.aligned.m16n8k16.row.col.f32.bf16.bf16.f32 "
        "{%0,%1,%2,%3}, {%4,%5,%6,%7}, {%8,%9}, {%0,%1,%2,%3};"
        : "+f"(d[0]), "+f"(d[1]), "+f"(d[2]), "+f"(d[3])
        : "r"(a[0]), "r"(a[1]), "r"(a[2]), "r"(a[3]), "r"(b[0]), "r"(b[1]));
}
__device__ __forceinline__ void splitbf2(float x, float y, unsigned& hi, unsigned& lo) {
    __nv_bfloat16 hx = __float2bfloat16_rn(x);
    __nv_bfloat16 hy = __float2bfloat16_rn(y);
    __nv_bfloat16 lx = __float2bfloat16_rn(x - __bfloat162float(hx));
    __nv_bfloat16 ly = __float2bfloat16_rn(y - __bfloat162float(hy));
    hi = (unsigned)__bfloat16_as_ushort(hx) | ((unsigned)__bfloat16_as_ushort(hy) << 16);
    lo = (unsigned)__bfloat16_as_ushort(lx) | ((unsigned)__bfloat16_as_ushort(ly) << 16);
}
__device__ __forceinline__ void cpasync16(void* sm, const void* gm) {
    unsigned a = (unsigned)__cvta_generic_to_shared(sm);
    asm volatile("cp.async.cg.shared.global [%0], [%1], 16;" :: "r"(a), "l"(gm));
}

// ---------------------------------------------------------------------------
// V projection (1xTF32), cp.async 4-stage pipeline, raw fp32 smem tiles.
// block 128x128, BK=16, 256 thr, warps 4(M)x2(N).
// ---------------------------------------------------------------------------
__global__ __launch_bounds__(256, 2)
void gemm_nt_tf32(const float* __restrict__ A, const float* __restrict__ W,
                  const float* __restrict__ bias, float* __restrict__ C) {
    extern __shared__ float vsm[];
    float* As2 = vsm;              // [VPSTG][128][20]
    float* Ws2 = vsm + VP_AS;      // [VPSTG][128][20]
    const int tid = threadIdx.x, lane = tid & 31, warp = tid >> 5;
    const int wm = (warp & 3) * 32, wn = (warp >> 2) * 64;
    const int row0 = blockIdx.y * 128, col0 = blockIdx.x * 128;
    const int ntiles = DMODEL / 16;

    auto prefetch = [&](int t) {
        int s = t & (VPSTG - 1);
        int k0 = t * 16;
        #pragma unroll
        for (int l = 0; l < 2; l++) {
            int c = tid + l * 256, r = c >> 2, qd = (c & 3) * 4;
            cpasync16(&As2[s*2560 + r*20 + qd], &A[(size_t)(row0+r)*DMODEL + k0 + qd]);
            cpasync16(&Ws2[s*2560 + r*20 + qd], &W[(size_t)(col0+r)*DMODEL + k0 + qd]);
        }
        asm volatile("cp.async.commit_group;");
    };
    #pragma unroll
    for (int t = 0; t < VPSTG - 1; t++) prefetch(t);

    float acc[2][8][4] = {};
    for (int t = 0; t < ntiles; t++) {
        int s = t & (VPSTG - 1);
        asm volatile("cp.async.wait_group %0;" :: "n"(VPSTG - 2));
        __syncthreads();
        const float* Ap = &As2[s*2560];
        const float* Wp = &Ws2[s*2560];
        #pragma unroll
        for (int kk = 0; kk < 16; kk += 8) {
            const int kr = kk + (lane & 3), m0 = wm + (lane >> 2);
            unsigned af[2][4];
            #pragma unroll
            for (int i = 0; i < 2; i++) {
                af[i][0] = __float_as_uint(Ap[(m0+i*16)*20 + kr]);
                af[i][1] = __float_as_uint(Ap[(m0+i*16+8)*20 + kr]);
                af[i][2] = __float_as_uint(Ap[(m0+i*16)*20 + kr+4]);
                af[i][3] = __float_as_uint(Ap[(m0+i*16+8)*20 + kr+4]);
            }
            #pragma unroll
            for (int j = 0; j < 8; j++) {
                int nb = wn + j * 8 + (lane >> 2);
                unsigned bf[2] = {__float_as_uint(Wp[nb*20 + kr]),
                                  __float_as_uint(Wp[nb*20 + kr+4])};
                mma8(acc[0][j], af[0], bf);
                mma8(acc[1][j], af[1], bf);
            }
        }
        __syncthreads();
        if (t + VPSTG - 1 < ntiles) prefetch(t + VPSTG - 1);
        else asm volatile("cp.async.commit_group;");
    }
    #pragma unroll
    for (int j = 0; j < 8; j++) {
        int c = col0 + wn + j * 8 + (lane & 3) * 2;
        float2 bb = *(const float2*)&bias[c];
        #pragma unroll
        for (int i = 0; i < 2; i++) {
            size_t r = row0 + wm + i * 16 + (lane >> 2);
            float2 o0 = {acc[i][j][0] + bb.x, acc[i][j][1] + bb.y};
            float2 o1 = {acc[i][j][2] + bb.x, acc[i][j][3] + bb.y};
            *(float2*)&C[r * DMODEL + c]       = o0;
            *(float2*)&C[(r + 8) * DMODEL + c] = o1;
        }
    }
}

// ---------------------------------------------------------------------------
// O projection: A = sum of SPLITK partial ctx buffers, register-pipelined.
// ---------------------------------------------------------------------------
__global__ __launch_bounds__(256, 2)
void gemm_o_tf32(const float* __restrict__ pctx, const float* __restrict__ W,
                 const float* __restrict__ bias, float* __restrict__ C) {
    __shared__ unsigned As[2][16][136];
    __shared__ unsigned Bs[2][16][136];
    const int tid = threadIdx.x, lane = tid & 31, warp = tid >> 5;
    const int wm = (warp & 3) * 32, wn = (warp >> 2) * 64;
    const int row0 = blockIdx.y * 128, col0 = blockIdx.x * 128;
    const size_t PS = (size_t)MROWS * DMODEL;

    float4 ra0[2], ra1[2], rb[2];
    auto doload = [&](int k0) {
        #pragma unroll
        for (int l = 0; l < 2; l++) {
            int idx = tid + l * 256, r = idx >> 2, kc = (idx & 3) << 2;
            size_t off = (size_t)(row0 + r) * DMODEL + k0 + kc;
            ra0[l] = *(const float4*)&pctx[off];
            ra1[l] = *(const float4*)&pctx[off + PS];
            rb[l]  = *(const float4*)&W[(size_t)(col0 + r) * DMODEL + k0 + kc];
        }
    };
    auto dostore = [&](int bf) {
        #pragma unroll
        for (int l = 0; l < 2; l++) {
            int idx = tid + l * 256, r = idx >> 2, kc = (idx & 3) << 2;
            float4 a4 = {ra0[l].x + ra1[l].x, ra0[l].y + ra1[l].y,
                         ra0[l].z + ra1[l].z, ra0[l].w + ra1[l].w};
            As[bf][kc+0][r]=f2tf(a4.x); As[bf][kc+1][r]=f2tf(a4.y);
            As[bf][kc+2][r]=f2tf(a4.z); As[bf][kc+3][r]=f2tf(a4.w);
            Bs[bf][kc+0][r]=f2tf(rb[l].x); Bs[bf][kc+1][r]=f2tf(rb[l].y);
            Bs[bf][kc+2][r]=f2tf(rb[l].z); Bs[bf][kc+3][r]=f2tf(rb[l].w);
        }
    };

    float acc[2][8][4] = {};
    doload(0); dostore(0); __syncthreads();
    int bf = 0;
    for (int k0 = 0; k0 < DMODEL; k0 += 16) {
        bool more = (k0 + 16 < DMODEL);
        if (more) doload(k0 + 16);
        #pragma unroll
        for (int kk = 0; kk < 16; kk += 8) {
            const int kr = kk + (lane & 3), m0 = wm + (lane >> 2);
            unsigned af[2][4];
            #pragma unroll
            for (int i = 0; i < 2; i++) {
                af[i][0] = As[bf][kr][m0 + i*16];     af[i][1] = As[bf][kr][m0 + i*16 + 8];
                af[i][2] = As[bf][kr+4][m0 + i*16];   af[i][3] = As[bf][kr+4][m0 + i*16 + 8];
            }
            #pragma unroll
            for (int j = 0; j < 8; j++) {
                int nb = wn + j * 8 + (lane >> 2);
                unsigned bfr[2] = {Bs[bf][kr][nb], Bs[bf][kr+4][nb]};
                mma8(acc[0][j], af[0], bfr);
                mma8(acc[1][j], af[1], bfr);
            }
        }
        if (more) { dostore(bf ^ 1); __syncthreads(); bf ^= 1; }
    }
    #pragma unroll
    for (int j = 0; j < 8; j++) {
        int c = col0 + wn + j * 8 + (lane & 3) * 2;
        float2 bb = *(const float2*)&bias[c];
        #pragma unroll
        for (int i = 0; i < 2; i++) {
            size_t r = row0 + wm + i * 16 + (lane >> 2);
            float2 o0 = {acc[i][j][0] + bb.x, acc[i][j][1] + bb.y};
            float2 o1 = {acc[i][j][2] + bb.x, acc[i][j][3] + bb.y};
            *(float2*)&C[r * DMODEL + c]       = o0;
            *(float2*)&C[(r + 8) * DMODEL + c] = o1;
        }
    }
}

// ---------------------------------------------------------------------------
// q+k projections, 3xBF16 split, register-pipelined, batched on blockIdx.z.
// ---------------------------------------------------------------------------
__global__ __launch_bounds__(256, 2)
void gemm_qk_bf16x3(const float* __restrict__ qin, const float* __restrict__ kin,
                    const float* __restrict__ wq, const float* __restrict__ wk,
                    const float* __restrict__ bq, const float* __restrict__ bk,
                    float* __restrict__ gq, float* __restrict__ gk) {
    const float* A    = blockIdx.z ? kin : qin;
    const float* W    = blockIdx.z ? wk  : wq;
    const float* bias = blockIdx.z ? bk  : bq;
    float* C          = blockIdx.z ? gk  : gq;

    __shared__ unsigned Ah2[2][8][132], Al2[2][8][132];
    __shared__ unsigned Bh2[2][8][132], Bl2[2][8][132];
    const int tid = threadIdx.x, lane = tid & 31, warp = tid >> 5;
    const int wm = (warp & 3) * 32, wn = (warp >> 2) * 64;
    const int row0 = blockIdx.y * 128, col0 = blockIdx.x * 128;
    const int kq = lane & 3;

    float4 ra[2], rb[2];
    auto doload = [&](int k0) {
        #pragma unroll
        for (int l = 0; l < 2; l++) {
            int idx = tid + l * 256, r = idx >> 2, kc = (idx & 3) << 2;
            ra[l] = *(const float4*)&A[(size_t)(row0 + r) * DMODEL + k0 + kc];
            rb[l] = *(const float4*)&W[(size_t)(col0 + r) * DMODEL + k0 + kc];
        }
    };
    auto dostore = [&](int bf) {
        #pragma unroll
        for (int l = 0; l < 2; l++) {
            int idx = tid + l * 256, r = idx >> 2, kc = (idx & 3) << 2, kp = kc >> 1;
            unsigned h0, l0, h1, l1;
            splitbf2(ra[l].x, ra[l].y, h0, l0); splitbf2(ra[l].z, ra[l].w, h1, l1);
            Ah2[bf][kp][r] = h0; Ah2[bf][kp+1][r] = h1;
            Al2[bf][kp][r] = l0; Al2[bf][kp+1][r] = l1;
            splitbf2(rb[l].x, rb[l].y, h0, l0); splitbf2(rb[l].z, rb[l].w, h1, l1);
            Bh2[bf][kp][r] = h0; Bh2[bf][kp+1][r] = h1;
            Bl2[bf][kp][r] = l0; Bl2[bf][kp+1][r] = l1;
        }
    };

    float acc[2][8][4] = {};
    doload(0); dostore(0); __syncthreads();
    int bf = 0;
    for (int k0 = 0; k0 < DMODEL; k0 += 16) {
        bool more = (k0 + 16 < DMODEL);
        if (more) doload(k0 + 16);
        unsigned ah[2][4], al[2][4];
        #pragma unroll
        for (int i = 0; i < 2; i++) {
            int m0 = wm + i * 16 + (lane >> 2);
            ah[i][0]=Ah2[bf][kq][m0];   ah[i][1]=Ah2[bf][kq][m0+8];
            ah[i][2]=Ah2[bf][kq+4][m0]; ah[i][3]=Ah2[bf][kq+4][m0+8];
            al[i][0]=Al2[bf][kq][m0];   al[i][1]=Al2[bf][kq][m0+8];
            al[i][2]=Al2[bf][kq+4][m0]; al[i][3]=Al2[bf][kq+4][m0+8];
        }
        #pragma unroll
        for (int j = 0; j < 8; j++) {
            int nb = wn + j * 8 + (lane >> 2);
            unsigned bh2[2] = {Bh2[bf][kq][nb], Bh2[bf][kq+4][nb]};
            unsigned bl2[2] = {Bl2[bf][kq][nb], Bl2[bf][kq+4][nb]};
            #pragma unroll
            for (int i = 0; i < 2; i++) {
                mma16(acc[i][j], al[i], bh2);
                mma16(acc[i][j], ah[i], bl2);
                mma16(acc[i][j], ah[i], bh2);
            }
        }
        if (more) { dostore(bf ^ 1); __syncthreads(); bf ^= 1; }
    }
    #pragma unroll
    for (int j = 0; j < 8; j++) {
        int c = col0 + wn + j * 8 + (lane & 3) * 2;
        float2 bb = *(const float2*)&bias[c];
        #pragma unroll
        for (int i = 0; i < 2; i++) {
            size_t r = row0 + wm + i * 16 + (lane >> 2);
            float2 o0 = {acc[i][j][0] + bb.x, acc[i][j][1] + bb.y};
            float2 o1 = {acc[i][j][2] + bb.x, acc[i][j][3] + bb.y};
            *(float2*)&C[r * DMODEL + c]       = o0;
            *(float2*)&C[(r + 8) * DMODEL + c] = o1;
        }
    }
}

// ---------------------------------------------------------------------------
// Fused scores (3xBF16) + mask + exp -> unnormalized P + rowsum partials.
// grid (NKT, 16, 32).
// ---------------------------------------------------------------------------
__global__ __launch_bounds__(256, 2)
void scores_exp(const float* __restrict__ gq, const float* __restrict__ gk,
                const int* __restrict__ mask, float* __restrict__ attn,
                float* __restrict__ partial) {
    extern __shared__ unsigned dsm[];
    unsigned (*Ah2)[132] = (unsigned(*)[132])dsm;        // [32][132]
    unsigned (*Al2)[132] = Ah2 + 32;
    unsigned (*Bh2)[132] = Al2 + 32;
    unsigned (*Bl2)[132] = Bh2 + 32;
    float* sums = (float*)(Bl2 + 32);                    // [2][128]

    const int tid = threadIdx.x, lane = tid & 31, warp = tid >> 5;
    const int wm = (warp & 3) * 32, wn = (warp >> 2) * 64;
    const int bh_i = blockIdx.z, b = bh_i >> 4, h = bh_i & 15;
    const int q0 = blockIdx.y * 128, c0 = blockIdx.x * 128;
    const float* Qb = gq + (size_t)b * SEQ * DMODEL + h * DHEAD;
    const float* Kb = gk + (size_t)b * SEQ * DMODEL + h * DHEAD;
    const int kq = lane & 3;

    #pragma unroll
    for (int l = 0; l < 8; l++) {
        int idx = tid + l * 256, r = idx >> 4, kc = (idx & 15) << 2, kp = kc >> 1;
        float4 a4 = *(const float4*)&Qb[(size_t)(q0 + r) * DMODEL + kc];
        float4 b4 = *(const float4*)&Kb[(size_t)(c0 + r) * DMODEL + kc];
        unsigned h0, l0, h1, l1;
        splitbf2(a4.x, a4.y, h0, l0); splitbf2(a4.z, a4.w, h1, l1);
        Ah2[kp][r] = h0; Ah2[kp+1][r] = h1; Al2[kp][r] = l0; Al2[kp+1][r] = l1;
        splitbf2(b4.x, b4.y, h0, l0); splitbf2(b4.z, b4.w, h1, l1);
        Bh2[kp][r] = h0; Bh2[kp+1][r] = h1; Bl2[kp][r] = l0; Bl2[kp+1][r] = l1;
    }
    __syncthreads();

    float acc[2][8][4] = {};
    #pragma unroll
    for (int kk = 0; kk < 32; kk += 8) {
        unsigned ah[2][4], al[2][4];
        #pragma unroll
        for (int i = 0; i < 2; i++) {
            int m0 = wm + i * 16 + (lane >> 2);
            ah[i][0]=Ah2[kk+kq][m0];   ah[i][1]=Ah2[kk+kq][m0+8];
            ah[i][2]=Ah2[kk+kq+4][m0]; ah[i][3]=Ah2[kk+kq+4][m0+8];
            al[i][0]=Al2[kk+kq][m0];   al[i][1]=Al2[kk+kq][m0+8];
            al[i][2]=Al2[kk+kq+4][m0]; al[i][3]=Al2[kk+kq+4][m0+8];
        }
        #pragma unroll
        for (int j = 0; j < 8; j++) {
            int nb = wn + j * 8 + (lane >> 2);
            unsigned bh2[2] = {Bh2[kk+kq][nb], Bh2[kk+kq+4][nb]};
            unsigned bl2[2] = {Bl2[kk+kq][nb], Bl2[kk+kq+4][nb]};
            #pragma unroll
            for (int i = 0; i < 2; i++) {
                mma16(acc[i][j], al[i], bh2);
                mma16(acc[i][j], ah[i], bl2);
                mma16(acc[i][j], ah[i], bh2);
            }
        }
    }

    const int* mrow = mask + (size_t)b * SEQ * SEQ;
    float* out = attn + (size_t)bh_i * SEQ * SEQ;
    float rs[2][2] = {};
    #pragma unroll
    for (int j = 0; j < 8; j++) {
        int c = c0 + wn + j * 8 + (lane & 3) * 2;
        #pragma unroll
        for (int i = 0; i < 2; i++) {
            size_t r = q0 + wm + i * 16 + (lane >> 2);
            int2 m0v = *(const int2*)&mrow[r * SEQ + c];
            int2 m1v = *(const int2*)&mrow[(r + 8) * SEQ + c];
            float2 o0, o1;
            o0.x = m0v.x ? __expf(acc[i][j][0] * 0.125f) : 0.f;
            o0.y = m0v.y ? __expf(acc[i][j][1] * 0.125f) : 0.f;
            o1.x = m1v.x ? __expf(acc[i][j][2] * 0.125f) : 0.f;
            o1.y = m1v.y ? __expf(acc[i][j][3] * 0.125f) : 0.f;
            *(float2*)&out[r * SEQ + c]       = o0;
            *(float2*)&out[(r + 8) * SEQ + c] = o1;
            rs[i][0] += o0.x + o0.y;
            rs[i][1] += o1.x + o1.y;
        }
    }
    #pragma unroll
    for (int i = 0; i < 2; i++)
        #pragma unroll
        for (int hh = 0; hh < 2; hh++) {
            float v = rs[i][hh];
            v += __shfl_xor_sync(0xffffffffu, v, 1);
            v += __shfl_xor_sync(0xffffffffu, v, 2);
            if ((lane & 3) == 0)
                sums[(warp >> 2) * 128 + wm + i * 16 + hh * 8 + (lane >> 2)] = v;
        }
    __syncthreads();
    if (tid < 128) {
        float tot = sums[tid] + sums[128 + tid];
        partial[((size_t)bh_i * SEQ + q0 + tid) * NKT + blockIdx.x] = tot;
    }
}

// ---------------------------------------------------------------------------
// Fused PV (tf32, split-K=2) with cp.async 4-stage pipeline.
// MMA consumes UNNORMALIZED P; accumulators scaled by inv rowsum at epilogue.
// Normalized P written to global from the smem tiles. grid (SPLITK, 16, 32).
// ---------------------------------------------------------------------------
__global__ __launch_bounds__(256, 3)
void pv_norm(float* __restrict__ attn, const float* __restrict__ gv,
             const float* __restrict__ partial, float* __restrict__ pctx) {
    extern __shared__ float psm[];
    float* Ps    = psm;                    // [PVSTG][128][20]
    float* Vs    = psm + PV_PS;            // [PVSTG][16][72]
    float* inv_s = psm + PV_PS + PV_VS;    // [128]

    const int tid = threadIdx.x, lane = tid & 31, warp = tid >> 5;
    const int wm = (warp & 3) * 32, wn = (warp >> 2) * 32;
    const int bh_i = blockIdx.z, b = bh_i >> 4, h = bh_i & 15;
    float* P = attn + (size_t)bh_i * SEQ * SEQ;
    const float* V = gv + (size_t)b * SEQ * DMODEL + h * DHEAD;
    float* Cc = pctx + (size_t)blockIdx.x * MROWS * DMODEL
                     + (size_t)b * SEQ * DMODEL + h * DHEAD;
    const int q0 = blockIdx.y * 128;
    const int kbase = blockIdx.x * (SEQ / SPLITK);
    const int ntiles = (SEQ / SPLITK) / 16;     // 64

    auto prefetch = [&](int t) {
        int s = t & (PVSTG - 1);
        int k0 = kbase + t * 16;
        #pragma unroll
        for (int l = 0; l < 2; l++) {
            int c = tid + l * 256, r = c >> 2, qd = (c & 3) * 4;
            cpasync16(&Ps[s*2560 + r*20 + qd], &P[(size_t)(q0+r)*SEQ + k0 + qd]);
        }
        {
            int kk = tid >> 4, n = (tid & 15) * 4;
            cpasync16(&Vs[s*1152 + kk*72 + n], &V[(size_t)(k0+kk)*DMODEL + n]);
        }
        asm volatile("cp.async.commit_group;");
    };
    #pragma unroll
    for (int t = 0; t < PVSTG - 1; t++) prefetch(t);

    if (tid < 128) {
        const float4* pp = (const float4*)&partial[((size_t)bh_i * SEQ + q0 + tid) * NKT];
        float4 p0 = pp[0], p1 = pp[1], p2 = pp[2], p3 = pp[3];
        float s = ((p0.x + p0.y) + (p0.z + p0.w)) + ((p1.x + p1.y) + (p1.z + p1.w))
                + ((p2.x + p2.y) + (p2.z + p2.w)) + ((p3.x + p3.y) + (p3.z + p3.w));
        inv_s[tid] = 1.0f / s;
    }

    float acc[2][4][4] = {};
    for (int t = 0; t < ntiles; t++) {
        int s = t & (PVSTG - 1);
        asm volatile("cp.async.wait_group %0;" :: "n"(PVSTG - 2));
        __syncthreads();
        const float* Pp = &Ps[s*2560];
        const float* Vp = &Vs[s*1152];
        #pragma unroll
        for (int kk = 0; kk < 16; kk += 8) {
            const int kr = kk + (lane & 3), m0 = wm + (lane >> 2);
            unsigned af[2][4];
            #pragma unroll
            for (int i = 0; i < 2; i++) {
                af[i][0] = __float_as_uint(Pp[(m0+i*16)*20 + kr]);
                af[i][1] = __float_as_uint(Pp[(m0+i*16+8)*20 + kr]);
                af[i][2] = __float_as_uint(Pp[(m0+i*16)*20 + kr+4]);
                af[i][3] = __float_as_uint(Pp[(m0+i*16+8)*20 + kr+4]);
            }
            #pragma unroll
            for (int j = 0; j < 4; j++) {
                int nb = wn + j * 8 + (lane >> 2);
                unsigned bfr[2] = {__float_as_uint(Vp[kr*72 + nb]),
                                   __float_as_uint(Vp[(kr+4)*72 + nb])};
                mma8(acc[0][j], af[0], bfr);
                mma8(acc[1][j], af[1], bfr);
            }
        }
        // write normalized attention from the smem tile
        {
            int k0 = kbase + t * 16;
            #pragma unroll
            for (int l = 0; l < 2; l++) {
                int c = tid + l * 256, r = c >> 2, qd = (c & 3) * 4;
                float4 a4 = *(const float4*)&Pp[r*20 + qd];
                float sc = inv_s[r];
                a4.x *= sc; a4.y *= sc; a4.z *= sc; a4.w *= sc;
                *(float4*)&P[(size_t)(q0+r)*SEQ + k0 + qd] = a4;
            }
        }
        __syncthreads();
        if (t + PVSTG - 1 < ntiles) prefetch(t + PVSTG - 1);
        else asm volatile("cp.async.commit_group;");
    }
    #pragma unroll
    for (int j = 0; j < 4; j++) {
        int c = wn + j * 8 + (lane & 3) * 2;
        #pragma unroll
        for (int i = 0; i < 2; i++) {
            int rl = wm + i * 16 + (lane >> 2);
            float sc0 = inv_s[rl], sc1 = inv_s[rl + 8];
            size_t r = q0 + rl;
            float2 o0 = {acc[i][j][0] * sc0, acc[i][j][1] * sc0};
            float2 o1 = {acc[i][j][2] * sc1, acc[i][j][3] * sc1};
            *(float2*)&Cc[r * DMODEL + c]       = o0;
            *(float2*)&Cc[(r + 8) * DMODEL + c] = o1;
        }
    }
}

// ---------------------------------------------------------------------------
// Residual + LayerNorm.
// ---------------------------------------------------------------------------
__global__ void ln_kernel(const float* __restrict__ resid,
                          const float* __restrict__ x,
                          const float* __restrict__ gamma,
                          const float* __restrict__ beta,
                          float* __restrict__ out) {
    const size_t row = blockIdx.x;
    const float4* xr = reinterpret_cast<const float4*>(x + row * DMODEL);
    const float4* rr = reinterpret_cast<const float4*>(resid + row * DMODEL);
    const int t = threadIdx.x;
    __shared__ float sred[8];

    float4 a = rr[t], bv = xr[t];
    float4 v = {a.x + bv.x, a.y + bv.y, a.z + bv.z, a.w + bv.w};
    float s = v.x + v.y + v.z + v.w;
    #pragma unroll
    for (int o = 16; o > 0; o >>= 1) s += __shfl_xor_sync(0xffffffffu, s, o);
    if ((t & 31) == 0) sred[t >> 5] = s;
    __syncthreads();
    float tot = 0.f;
    #pragma unroll
    for (int i = 0; i < 8; i++) tot += sred[i];
    const float mu = tot * (1.0f / DMODEL);
    __syncthreads();

    float dx = v.x - mu, dy = v.y - mu, dz = v.z - mu, dw = v.w - mu;
    float sq = dx*dx + dy*dy + dz*dz + dw*dw;
    #pragma unroll
    for (int o = 16; o > 0; o >>= 1) sq += __shfl_xor_sync(0xffffffffu, sq, o);
    if ((t & 31) == 0) sred[t >> 5] = sq;
    __syncthreads();
    float tot2 = 0.f;
    #pragma unroll
    for (int i = 0; i < 8; i++) tot2 += sred[i];
    const float inv = rsqrtf(tot2 * (1.0f / DMODEL) + 1e-5f);

    float4 g = reinterpret_cast<const float4*>(gamma)[t];
    float4 be = reinterpret_cast<const float4*>(beta)[t];
    float4 o;
    o.x = dx * inv * g.x + be.x;
    o.y = dy * inv * g.y + be.y;
    o.z = dz * inv * g.z + be.z;
    o.w = dw * inv * g.w + be.w;
    reinterpret_cast<float4*>(out + row * DMODEL)[t] = o;
}

// ---------------------------------------------------------------------------
extern "C" void kernel_launch(void* const* d_in, const int* in_sizes, int n_in,
                              void* d_out, int out_size) {
    const float* q     = (const float*)d_in[0];
    const float* k     = (const float*)d_in[1];
    const float* v     = (const float*)d_in[2];
    const int*   mask  = (const int*)  d_in[3];
    const float* wq    = (const float*)d_in[4];
    const float* bq    = (const float*)d_in[5];
    const float* wk    = (const float*)d_in[6];
    const float* bk    = (const float*)d_in[7];
    const float* wv    = (const float*)d_in[8];
    const float* bv    = (const float*)d_in[9];
    const float* wo    = (const float*)d_in[10];
    const float* bo    = (const float*)d_in[11];
    const float* gamma = (const float*)d_in[12];
    const float* beta  = (const float*)d_in[13];

    float* out  = (float*)d_out;
    float* attn = out + ATT_OFF;

    void* sp = nullptr;
    cudaGetSymbolAddress(&sp, g_scratch);
    const size_t PS = (size_t)MROWS * DMODEL;
    float* gq      = (float*)sp;
    float* gk      = gq + PS;
    float* gv      = gk + PS;
    float* go      = gv + PS;
    float* pctx    = go + PS;            // SPLITK x PS
    float* partial = pctx + SPLITK * PS;

    cudaFuncSetAttribute(scores_exp,   cudaFuncAttributeMaxDynamicSharedMemorySize, SC_SMEM);
    cudaFuncSetAttribute(pv_norm,      cudaFuncAttributeMaxDynamicSharedMemorySize, PV_SMEM);
    cudaFuncSetAttribute(gemm_nt_tf32, cudaFuncAttributeMaxDynamicSharedMemorySize, VP_SMEM);

    dim3 gQK(DMODEL / 128, MROWS / 128, 2);             // (8, 32, 2)
    gemm_qk_bf16x3<<<gQK, 256>>>(q, k, wq, wk, bq, bk, gq, gk);

    dim3 gProj(DMODEL / 128, MROWS / 128);              // (8, 32)
    gemm_nt_tf32<<<gProj, 256, VP_SMEM>>>(v, wv, bv, gv);

    dim3 gScores(NKT, SEQ / 128, BATCH * NHEADS);       // (16, 16, 32)
    scores_exp<<<gScores, 256, SC_SMEM>>>(gq, gk, mask, attn, partial);

    dim3 gPV(SPLITK, SEQ / 128, BATCH * NHEADS);        // (2, 16, 32)
    pv_norm<<<gPV, 256, PV_SMEM>>>(attn, gv, partial, pctx);

    gemm_o_tf32<<<gProj, 256>>>(pctx, wo, bo, go);

    ln_kernel<<<MROWS, 256>>>(q, go, gamma, beta, out);
}

// round 8
// speedup vs baseline: 3.1031x; 1.0145x over previous
#include <cuda_runtime.h>
#include <cuda_bf16.h>
#include <math.h>

#define BATCH 2
#define SEQ   2048
#define DMODEL 1024
#define NHEADS 16
#define DHEAD  64
#define MROWS (BATCH*SEQ)                    // 4096
#define ATT_OFF ((size_t)BATCH*SEQ*DMODEL)
#define NKT 16                               // key tiles in scores grid
#define SPLITK 2                             // pv split-K factor
#define PVSTG 3
#define VPSTG 4

// gq, gk, gv, go (4 x PS) + pctx (2 x PS) + rowsum partials
__device__ float g_scratch[6ull * MROWS * DMODEL + (size_t)BATCH * NHEADS * SEQ * NKT];

// scores_exp dynamic smem: 4 strip arrays [32][132] u32 + sums [2][128]
#define SC_SMEM (4 * 32 * 132 * 4 + 2 * 128 * 4)
// pv dynamic smem: P stages [3][128][20] + V stages [3][16][72] + inv_s[128]
#define PV_PS   (PVSTG * 128 * 20)
#define PV_VS   (PVSTG * 16 * 72)
#define PV_SMEM ((PV_PS + PV_VS + 128) * 4)
// vproj dynamic smem: A + W stages [4][128][20] each
#define VP_AS   (VPSTG * 128 * 20)
#define VP_SMEM (2 * VP_AS * 4)

// ---------------------------------------------------------------------------
__device__ __forceinline__ unsigned f2tf(float x) {
    unsigned r;
    asm("cvt.rna.tf32.f32 %0, %1;" : "=r"(r) : "f"(x));
    return r;
}
__device__ __forceinline__ void mma8(float* d, const unsigned* a, const unsigned* b) {
    asm volatile(
        "mma.sync.aligned.m16n8k8.row.col.f32.tf32.tf32.f32 "
        "{%0,%1,%2,%3}, {%4,%5,%6,%7}, {%8,%9}, {%0,%1,%2,%3};"
        : "+f"(d[0]), "+f"(d[1]), "+f"(d[2]), "+f"(d[3])
        : "r"(a[0]), "r"(a[1]), "r"(a[2]), "r"(a[3]), "r"(b[0]), "r"(b[1]));
}
__device__ __forceinline__ void mma16(float* d, const unsigned* a, const unsigned* b) {
    asm volatile(
        "mma.sync.aligned.m16n8k16.row.col.f32.bf16.bf16.f32 "
        "{%0,%1,%2,%3}, {%4,%5,%6,%7}, {%8,%9}, {%0,%1,%2,%3};"
        : "+f"(d[0]), "+f"(d[1]), "+f"(d[2]), "+f"(d[3])
        : "r"(a[0]), "r"(a[1]), "r"(a[2]), "r"(a[3]), "r"(b[0]), "r"(b[1]));
}
__device__ __forceinline__ void splitbf2(float x, float y, unsigned& hi, unsigned& lo) {
    __nv_bfloat16 hx = __float2bfloat16_rn(x);
    __nv_bfloat16 hy = __float2bfloat16_rn(y);
    __nv_bfloat16 lx = __float2bfloat16_rn(x - __bfloat162float(hx));
    __nv_bfloat16 ly = __float2bfloat16_rn(y - __bfloat162float(hy));
    hi = (unsigned)__bfloat16_as_ushort(hx) | ((unsigned)__bfloat16_as_ushort(hy) << 16);
    lo = (unsigned)__bfloat16_as_ushort(lx) | ((unsigned)__bfloat16_as_ushort(ly) << 16);
}
__device__ __forceinline__ void cpasync16(void* sm, const void* gm) {
    unsigned a = (unsigned)__cvta_generic_to_shared(sm);
    asm volatile("cp.async.cg.shared.global [%0], [%1], 16;" :: "r"(a), "l"(gm));
}

// ---------------------------------------------------------------------------
// V projection (1xTF32), cp.async 4-stage pipeline, raw fp32 smem tiles.
// ---------------------------------------------------------------------------
__global__ __launch_bounds__(256, 2)
void gemm_nt_tf32(const float* __restrict__ A, const float* __restrict__ W,
                  const float* __restrict__ bias, float* __restrict__ C) {
    extern __shared__ float vsm[];
    float* As2 = vsm;              // [VPSTG][128][20]
    float* Ws2 = vsm + VP_AS;      // [VPSTG][128][20]
    const int tid = threadIdx.x, lane = tid & 31, warp = tid >> 5;
    const int wm = (warp & 3) * 32, wn = (warp >> 2) * 64;
    const int row0 = blockIdx.y * 128, col0 = blockIdx.x * 128;
    const int ntiles = DMODEL / 16;

    auto prefetch = [&](int t) {
        int s = t & (VPSTG - 1);
        int k0 = t * 16;
        #pragma unroll
        for (int l = 0; l < 2; l++) {
            int c = tid + l * 256, r = c >> 2, qd = (c & 3) * 4;
            cpasync16(&As2[s*2560 + r*20 + qd], &A[(size_t)(row0+r)*DMODEL + k0 + qd]);
            cpasync16(&Ws2[s*2560 + r*20 + qd], &W[(size_t)(col0+r)*DMODEL + k0 + qd]);
        }
        asm volatile("cp.async.commit_group;");
    };
    #pragma unroll
    for (int t = 0; t < VPSTG - 1; t++) prefetch(t);

    float acc[2][8][4] = {};
    for (int t = 0; t < ntiles; t++) {
        int s = t & (VPSTG - 1);
        asm volatile("cp.async.wait_group %0;" :: "n"(VPSTG - 2));
        __syncthreads();
        const float* Ap = &As2[s*2560];
        const float* Wp = &Ws2[s*2560];
        #pragma unroll
        for (int kk = 0; kk < 16; kk += 8) {
            const int kr = kk + (lane & 3), m0 = wm + (lane >> 2);
            unsigned af[2][4];
            #pragma unroll
            for (int i = 0; i < 2; i++) {
                af[i][0] = __float_as_uint(Ap[(m0+i*16)*20 + kr]);
                af[i][1] = __float_as_uint(Ap[(m0+i*16+8)*20 + kr]);
                af[i][2] = __float_as_uint(Ap[(m0+i*16)*20 + kr+4]);
                af[i][3] = __float_as_uint(Ap[(m0+i*16+8)*20 + kr+4]);
            }
            #pragma unroll
            for (int j = 0; j < 8; j++) {
                int nb = wn + j * 8 + (lane >> 2);
                unsigned bf[2] = {__float_as_uint(Wp[nb*20 + kr]),
                                  __float_as_uint(Wp[nb*20 + kr+4])};
                mma8(acc[0][j], af[0], bf);
                mma8(acc[1][j], af[1], bf);
            }
        }
        __syncthreads();
        if (t + VPSTG - 1 < ntiles) prefetch(t + VPSTG - 1);
        else asm volatile("cp.async.commit_group;");
    }
    #pragma unroll
    for (int j = 0; j < 8; j++) {
        int c = col0 + wn + j * 8 + (lane & 3) * 2;
        float2 bb = *(const float2*)&bias[c];
        #pragma unroll
        for (int i = 0; i < 2; i++) {
            size_t r = row0 + wm + i * 16 + (lane >> 2);
            float2 o0 = {acc[i][j][0] + bb.x, acc[i][j][1] + bb.y};
            float2 o1 = {acc[i][j][2] + bb.x, acc[i][j][3] + bb.y};
            *(float2*)&C[r * DMODEL + c]       = o0;
            *(float2*)&C[(r + 8) * DMODEL + c] = o1;
        }
    }
}

// ---------------------------------------------------------------------------
// O projection: A = sum of SPLITK partial ctx buffers, register-pipelined.
// ---------------------------------------------------------------------------
__global__ __launch_bounds__(256, 2)
void gemm_o_tf32(const float* __restrict__ pctx, const float* __restrict__ W,
                 const float* __restrict__ bias, float* __restrict__ C) {
    __shared__ unsigned As[2][16][136];
    __shared__ unsigned Bs[2][16][136];
    const int tid = threadIdx.x, lane = tid & 31, warp = tid >> 5;
    const int wm = (warp & 3) * 32, wn = (warp >> 2) * 64;
    const int row0 = blockIdx.y * 128, col0 = blockIdx.x * 128;
    const size_t PS = (size_t)MROWS * DMODEL;

    float4 ra0[2], ra1[2], rb[2];
    auto doload = [&](int k0) {
        #pragma unroll
        for (int l = 0; l < 2; l++) {
            int idx = tid + l * 256, r = idx >> 2, kc = (idx & 3) << 2;
            size_t off = (size_t)(row0 + r) * DMODEL + k0 + kc;
            ra0[l] = *(const float4*)&pctx[off];
            ra1[l] = *(const float4*)&pctx[off + PS];
            rb[l]  = *(const float4*)&W[(size_t)(col0 + r) * DMODEL + k0 + kc];
        }
    };
    auto dostore = [&](int bf) {
        #pragma unroll
        for (int l = 0; l < 2; l++) {
            int idx = tid + l * 256, r = idx >> 2, kc = (idx & 3) << 2;
            float4 a4 = {ra0[l].x + ra1[l].x, ra0[l].y + ra1[l].y,
                         ra0[l].z + ra1[l].z, ra0[l].w + ra1[l].w};
            As[bf][kc+0][r]=f2tf(a4.x); As[bf][kc+1][r]=f2tf(a4.y);
            As[bf][kc+2][r]=f2tf(a4.z); As[bf][kc+3][r]=f2tf(a4.w);
            Bs[bf][kc+0][r]=f2tf(rb[l].x); Bs[bf][kc+1][r]=f2tf(rb[l].y);
            Bs[bf][kc+2][r]=f2tf(rb[l].z); Bs[bf][kc+3][r]=f2tf(rb[l].w);
        }
    };

    float acc[2][8][4] = {};
    doload(0); dostore(0); __syncthreads();
    int bf = 0;
    for (int k0 = 0; k0 < DMODEL; k0 += 16) {
        bool more = (k0 + 16 < DMODEL);
        if (more) doload(k0 + 16);
        #pragma unroll
        for (int kk = 0; kk < 16; kk += 8) {
            const int kr = kk + (lane & 3), m0 = wm + (lane >> 2);
            unsigned af[2][4];
            #pragma unroll
            for (int i = 0; i < 2; i++) {
                af[i][0] = As[bf][kr][m0 + i*16];     af[i][1] = As[bf][kr][m0 + i*16 + 8];
                af[i][2] = As[bf][kr+4][m0 + i*16];   af[i][3] = As[bf][kr+4][m0 + i*16 + 8];
            }
            #pragma unroll
            for (int j = 0; j < 8; j++) {
                int nb = wn + j * 8 + (lane >> 2);
                unsigned bfr[2] = {Bs[bf][kr][nb], Bs[bf][kr+4][nb]};
                mma8(acc[0][j], af[0], bfr);
                mma8(acc[1][j], af[1], bfr);
            }
        }
        if (more) { dostore(bf ^ 1); __syncthreads(); bf ^= 1; }
    }
    #pragma unroll
    for (int j = 0; j < 8; j++) {
        int c = col0 + wn + j * 8 + (lane & 3) * 2;
        float2 bb = *(const float2*)&bias[c];
        #pragma unroll
        for (int i = 0; i < 2; i++) {
            size_t r = row0 + wm + i * 16 + (lane >> 2);
            float2 o0 = {acc[i][j][0] + bb.x, acc[i][j][1] + bb.y};
            float2 o1 = {acc[i][j][2] + bb.x, acc[i][j][3] + bb.y};
            *(float2*)&C[r * DMODEL + c]       = o0;
            *(float2*)&C[(r + 8) * DMODEL + c] = o1;
        }
    }
}

// ---------------------------------------------------------------------------
// q+k projections, 3xBF16 split, register-pipelined, batched on blockIdx.z.
// ---------------------------------------------------------------------------
__global__ __launch_bounds__(256, 2)
void gemm_qk_bf16x3(const float* __restrict__ qin, const float* __restrict__ kin,
                    const float* __restrict__ wq, const float* __restrict__ wk,
                    const float* __restrict__ bq, const float* __restrict__ bk,
                    float* __restrict__ gq, float* __restrict__ gk) {
    const float* A    = blockIdx.z ? kin : qin;
    const float* W    = blockIdx.z ? wk  : wq;
    const float* bias = blockIdx.z ? bk  : bq;
    float* C          = blockIdx.z ? gk  : gq;

    __shared__ unsigned Ah2[2][8][132], Al2[2][8][132];
    __shared__ unsigned Bh2[2][8][132], Bl2[2][8][132];
    const int tid = threadIdx.x, lane = tid & 31, warp = tid >> 5;
    const int wm = (warp & 3) * 32, wn = (warp >> 2) * 64;
    const int row0 = blockIdx.y * 128, col0 = blockIdx.x * 128;
    const int kq = lane & 3;

    float4 ra[2], rb[2];
    auto doload = [&](int k0) {
        #pragma unroll
        for (int l = 0; l < 2; l++) {
            int idx = tid + l * 256, r = idx >> 2, kc = (idx & 3) << 2;
            ra[l] = *(const float4*)&A[(size_t)(row0 + r) * DMODEL + k0 + kc];
            rb[l] = *(const float4*)&W[(size_t)(col0 + r) * DMODEL + k0 + kc];
        }
    };
    auto dostore = [&](int bf) {
        #pragma unroll
        for (int l = 0; l < 2; l++) {
            int idx = tid + l * 256, r = idx >> 2, kc = (idx & 3) << 2, kp = kc >> 1;
            unsigned h0, l0, h1, l1;
            splitbf2(ra[l].x, ra[l].y, h0, l0); splitbf2(ra[l].z, ra[l].w, h1, l1);
            Ah2[bf][kp][r] = h0; Ah2[bf][kp+1][r] = h1;
            Al2[bf][kp][r] = l0; Al2[bf][kp+1][r] = l1;
            splitbf2(rb[l].x, rb[l].y, h0, l0); splitbf2(rb[l].z, rb[l].w, h1, l1);
            Bh2[bf][kp][r] = h0; Bh2[bf][kp+1][r] = h1;
            Bl2[bf][kp][r] = l0; Bl2[bf][kp+1][r] = l1;
        }
    };

    float acc[2][8][4] = {};
    doload(0); dostore(0); __syncthreads();
    int bf = 0;
    for (int k0 = 0; k0 < DMODEL; k0 += 16) {
        bool more = (k0 + 16 < DMODEL);
        if (more) doload(k0 + 16);
        unsigned ah[2][4], al[2][4];
        #pragma unroll
        for (int i = 0; i < 2; i++) {
            int m0 = wm + i * 16 + (lane >> 2);
            ah[i][0]=Ah2[bf][kq][m0];   ah[i][1]=Ah2[bf][kq][m0+8];
            ah[i][2]=Ah2[bf][kq+4][m0]; ah[i][3]=Ah2[bf][kq+4][m0+8];
            al[i][0]=Al2[bf][kq][m0];   al[i][1]=Al2[bf][kq][m0+8];
            al[i][2]=Al2[bf][kq+4][m0]; al[i][3]=Al2[bf][kq+4][m0+8];
        }
        #pragma unroll
        for (int j = 0; j < 8; j++) {
            int nb = wn + j * 8 + (lane >> 2);
            unsigned bh2[2] = {Bh2[bf][kq][nb], Bh2[bf][kq+4][nb]};
            unsigned bl2[2] = {Bl2[bf][kq][nb], Bl2[bf][kq+4][nb]};
            #pragma unroll
            for (int i = 0; i < 2; i++) {
                mma16(acc[i][j], al[i], bh2);
                mma16(acc[i][j], ah[i], bl2);
                mma16(acc[i][j], ah[i], bh2);
            }
        }
        if (more) { dostore(bf ^ 1); __syncthreads(); bf ^= 1; }
    }
    #pragma unroll
    for (int j = 0; j < 8; j++) {
        int c = col0 + wn + j * 8 + (lane & 3) * 2;
        float2 bb = *(const float2*)&bias[c];
        #pragma unroll
        for (int i = 0; i < 2; i++) {
            size_t r = row0 + wm + i * 16 + (lane >> 2);
            float2 o0 = {acc[i][j][0] + bb.x, acc[i][j][1] + bb.y};
            float2 o1 = {acc[i][j][2] + bb.x, acc[i][j][3] + bb.y};
            *(float2*)&C[r * DMODEL + c]       = o0;
            *(float2*)&C[(r + 8) * DMODEL + c] = o1;
        }
    }
}

// ---------------------------------------------------------------------------
// Fused scores (3xBF16) + mask + exp -> unnormalized P + rowsum partials.
// grid (32 bh, NKT ktile, 16 qtile): bh fastest so all 16 heads of a batch
// share the same mask tile in L2 (16x mask traffic reduction).
// ---------------------------------------------------------------------------
__global__ __launch_bounds__(256, 2)
void scores_exp(const float* __restrict__ gq, const float* __restrict__ gk,
                const int* __restrict__ mask, float* __restrict__ attn,
                float* __restrict__ partial) {
    extern __shared__ unsigned dsm[];
    unsigned (*Ah2)[132] = (unsigned(*)[132])dsm;        // [32][132]
    unsigned (*Al2)[132] = Ah2 + 32;
    unsigned (*Bh2)[132] = Al2 + 32;
    unsigned (*Bl2)[132] = Bh2 + 32;
    float* sums = (float*)(Bl2 + 32);                    // [2][128]

    const int tid = threadIdx.x, lane = tid & 31, warp = tid >> 5;
    const int wm = (warp & 3) * 32, wn = (warp >> 2) * 64;
    const int bh_i = blockIdx.x, b = bh_i >> 4, h = bh_i & 15;
    const int ktile = blockIdx.y;
    const int c0 = ktile * 128, q0 = blockIdx.z * 128;
    const float* Qb = gq + (size_t)b * SEQ * DMODEL + h * DHEAD;
    const float* Kb = gk + (size_t)b * SEQ * DMODEL + h * DHEAD;
    const int kq = lane & 3;

    #pragma unroll
    for (int l = 0; l < 8; l++) {
        int idx = tid + l * 256, r = idx >> 4, kc = (idx & 15) << 2, kp = kc >> 1;
        float4 a4 = *(const float4*)&Qb[(size_t)(q0 + r) * DMODEL + kc];
        float4 b4 = *(const float4*)&Kb[(size_t)(c0 + r) * DMODEL + kc];
        unsigned h0, l0, h1, l1;
        splitbf2(a4.x, a4.y, h0, l0); splitbf2(a4.z, a4.w, h1, l1);
        Ah2[kp][r] = h0; Ah2[kp+1][r] = h1; Al2[kp][r] = l0; Al2[kp+1][r] = l1;
        splitbf2(b4.x, b4.y, h0, l0); splitbf2(b4.z, b4.w, h1, l1);
        Bh2[kp][r] = h0; Bh2[kp+1][r] = h1; Bl2[kp][r] = l0; Bl2[kp+1][r] = l1;
    }
    __syncthreads();

    float acc[2][8][4] = {};
    #pragma unroll
    for (int kk = 0; kk < 32; kk += 8) {
        unsigned ah[2][4], al[2][4];
        #pragma unroll
        for (int i = 0; i < 2; i++) {
            int m0 = wm + i * 16 + (lane >> 2);
            ah[i][0]=Ah2[kk+kq][m0];   ah[i][1]=Ah2[kk+kq][m0+8];
            ah[i][2]=Ah2[kk+kq+4][m0]; ah[i][3]=Ah2[kk+kq+4][m0+8];
            al[i][0]=Al2[kk+kq][m0];   al[i][1]=Al2[kk+kq][m0+8];
            al[i][2]=Al2[kk+kq+4][m0]; al[i][3]=Al2[kk+kq+4][m0+8];
        }
        #pragma unroll
        for (int j = 0; j < 8; j++) {
            int nb = wn + j * 8 + (lane >> 2);
            unsigned bh2[2] = {Bh2[kk+kq][nb], Bh2[kk+kq+4][nb]};
            unsigned bl2[2] = {Bl2[kk+kq][nb], Bl2[kk+kq+4][nb]};
            #pragma unroll
            for (int i = 0; i < 2; i++) {
                mma16(acc[i][j], al[i], bh2);
                mma16(acc[i][j], ah[i], bl2);
                mma16(acc[i][j], ah[i], bh2);
            }
        }
    }

    const int* mrow = mask + (size_t)b * SEQ * SEQ;
    float* out = attn + (size_t)bh_i * SEQ * SEQ;
    float rs[2][2] = {};
    #pragma unroll
    for (int j = 0; j < 8; j++) {
        int c = c0 + wn + j * 8 + (lane & 3) * 2;
        #pragma unroll
        for (int i = 0; i < 2; i++) {
            size_t r = q0 + wm + i * 16 + (lane >> 2);
            int2 m0v = *(const int2*)&mrow[r * SEQ + c];
            int2 m1v = *(const int2*)&mrow[(r + 8) * SEQ + c];
            float2 o0, o1;
            o0.x = m0v.x ? __expf(acc[i][j][0] * 0.125f) : 0.f;
            o0.y = m0v.y ? __expf(acc[i][j][1] * 0.125f) : 0.f;
            o1.x = m1v.x ? __expf(acc[i][j][2] * 0.125f) : 0.f;
            o1.y = m1v.y ? __expf(acc[i][j][3] * 0.125f) : 0.f;
            *(float2*)&out[r * SEQ + c]       = o0;
            *(float2*)&out[(r + 8) * SEQ + c] = o1;
            rs[i][0] += o0.x + o0.y;
            rs[i][1] += o1.x + o1.y;
        }
    }
    #pragma unroll
    for (int i = 0; i < 2; i++)
        #pragma unroll
        for (int hh = 0; hh < 2; hh++) {
            float v = rs[i][hh];
            v += __shfl_xor_sync(0xffffffffu, v, 1);
            v += __shfl_xor_sync(0xffffffffu, v, 2);
            if ((lane & 3) == 0)
                sums[(warp >> 2) * 128 + wm + i * 16 + hh * 8 + (lane >> 2)] = v;
        }
    __syncthreads();
    if (tid < 128) {
        float tot = sums[tid] + sums[128 + tid];
        partial[((size_t)bh_i * SEQ + q0 + tid) * NKT + ktile] = tot;
    }
}

// ---------------------------------------------------------------------------
// Fused PV (tf32, split-K=2) with cp.async 3-stage pipeline, 4 CTAs/SM.
// MMA consumes UNNORMALIZED P; accumulators scaled by inv rowsum at epilogue.
// Normalized P written to global from the smem tiles. grid (SPLITK, 16, 32).
// ---------------------------------------------------------------------------
__global__ __launch_bounds__(256, 4)
void pv_norm(float* __restrict__ attn, const float* __restrict__ gv,
             const float* __restrict__ partial, float* __restrict__ pctx) {
    extern __shared__ float psm[];
    float* Ps    = psm;                    // [PVSTG][128][20]
    float* Vs    = psm + PV_PS;            // [PVSTG][16][72]
    float* inv_s = psm + PV_PS + PV_VS;    // [128]

    const int tid = threadIdx.x, lane = tid & 31, warp = tid >> 5;
    const int wm = (warp & 3) * 32, wn = (warp >> 2) * 32;
    const int bh_i = blockIdx.z, b = bh_i >> 4, h = bh_i & 15;
    float* P = attn + (size_t)bh_i * SEQ * SEQ;
    const float* V = gv + (size_t)b * SEQ * DMODEL + h * DHEAD;
    float* Cc = pctx + (size_t)blockIdx.x * MROWS * DMODEL
                     + (size_t)b * SEQ * DMODEL + h * DHEAD;
    const int q0 = blockIdx.y * 128;
    const int kbase = blockIdx.x * (SEQ / SPLITK);
    const int ntiles = (SEQ / SPLITK) / 16;     // 64

    auto prefetch = [&](int t) {
        int s = t % PVSTG;
        int k0 = kbase + t * 16;
        #pragma unroll
        for (int l = 0; l < 2; l++) {
            int c = tid + l * 256, r = c >> 2, qd = (c & 3) * 4;
            cpasync16(&Ps[s*2560 + r*20 + qd], &P[(size_t)(q0+r)*SEQ + k0 + qd]);
        }
        {
            int kk = tid >> 4, n = (tid & 15) * 4;
            cpasync16(&Vs[s*1152 + kk*72 + n], &V[(size_t)(k0+kk)*DMODEL + n]);
        }
        asm volatile("cp.async.commit_group;");
    };
    #pragma unroll
    for (int t = 0; t < PVSTG - 1; t++) prefetch(t);

    if (tid < 128) {
        const float4* pp = (const float4*)&partial[((size_t)bh_i * SEQ + q0 + tid) * NKT];
        float4 p0 = pp[0], p1 = pp[1], p2 = pp[2], p3 = pp[3];
        float s = ((p0.x + p0.y) + (p0.z + p0.w)) + ((p1.x + p1.y) + (p1.z + p1.w))
                + ((p2.x + p2.y) + (p2.z + p2.w)) + ((p3.x + p3.y) + (p3.z + p3.w));
        inv_s[tid] = 1.0f / s;
    }

    float acc[2][4][4] = {};
    for (int t = 0; t < ntiles; t++) {
        int s = t % PVSTG;
        asm volatile("cp.async.wait_group %0;" :: "n"(PVSTG - 2));
        __syncthreads();
        const float* Pp = &Ps[s*2560];
        const float* Vp = &Vs[s*1152];
        #pragma unroll
        for (int kk = 0; kk < 16; kk += 8) {
            const int kr = kk + (lane & 3), m0 = wm + (lane >> 2);
            unsigned af[2][4];
            #pragma unroll
            for (int i = 0; i < 2; i++) {
                af[i][0] = __float_as_uint(Pp[(m0+i*16)*20 + kr]);
                af[i][1] = __float_as_uint(Pp[(m0+i*16+8)*20 + kr]);
                af[i][2] = __float_as_uint(Pp[(m0+i*16)*20 + kr+4]);
                af[i][3] = __float_as_uint(Pp[(m0+i*16+8)*20 + kr+4]);
            }
            #pragma unroll
            for (int j = 0; j < 4; j++) {
                int nb = wn + j * 8 + (lane >> 2);
                unsigned bfr[2] = {__float_as_uint(Vp[kr*72 + nb]),
                                   __float_as_uint(Vp[(kr+4)*72 + nb])};
                mma8(acc[0][j], af[0], bfr);
                mma8(acc[1][j], af[1], bfr);
            }
        }
        // write normalized attention from the smem tile
        {
            int k0 = kbase + t * 16;
            #pragma unroll
            for (int l = 0; l < 2; l++) {
                int c = tid + l * 256, r = c >> 2, qd = (c & 3) * 4;
                float4 a4 = *(const float4*)&Pp[r*20 + qd];
                float sc = inv_s[r];
                a4.x *= sc; a4.y *= sc; a4.z *= sc; a4.w *= sc;
                *(float4*)&P[(size_t)(q0+r)*SEQ + k0 + qd] = a4;
            }
        }
        __syncthreads();
        if (t + PVSTG - 1 < ntiles) prefetch(t + PVSTG - 1);
        else asm volatile("cp.async.commit_group;");
    }
    #pragma unroll
    for (int j = 0; j < 4; j++) {
        int c = wn + j * 8 + (lane & 3) * 2;
        #pragma unroll
        for (int i = 0; i < 2; i++) {
            int rl = wm + i * 16 + (lane >> 2);
            float sc0 = inv_s[rl], sc1 = inv_s[rl + 8];
            size_t r = q0 + rl;
            float2 o0 = {acc[i][j][0] * sc0, acc[i][j][1] * sc0};
            float2 o1 = {acc[i][j][2] * sc1, acc[i][j][3] * sc1};
            *(float2*)&Cc[r * DMODEL + c]       = o0;
            *(float2*)&Cc[(r + 8) * DMODEL + c] = o1;
        }
    }
}

// ---------------------------------------------------------------------------
// Residual + LayerNorm.
// ---------------------------------------------------------------------------
__global__ void ln_kernel(const float* __restrict__ resid,
                          const float* __restrict__ x,
                          const float* __restrict__ gamma,
                          const float* __restrict__ beta,
                          float* __restrict__ out) {
    const size_t row = blockIdx.x;
    const float4* xr = reinterpret_cast<const float4*>(x + row * DMODEL);
    const float4* rr = reinterpret_cast<const float4*>(resid + row * DMODEL);
    const int t = threadIdx.x;
    __shared__ float sred[8];

    float4 a = rr[t], bv = xr[t];
    float4 v = {a.x + bv.x, a.y + bv.y, a.z + bv.z, a.w + bv.w};
    float s = v.x + v.y + v.z + v.w;
    #pragma unroll
    for (int o = 16; o > 0; o >>= 1) s += __shfl_xor_sync(0xffffffffu, s, o);
    if ((t & 31) == 0) sred[t >> 5] = s;
    __syncthreads();
    float tot = 0.f;
    #pragma unroll
    for (int i = 0; i < 8; i++) tot += sred[i];
    const float mu = tot * (1.0f / DMODEL);
    __syncthreads();

    float dx = v.x - mu, dy = v.y - mu, dz = v.z - mu, dw = v.w - mu;
    float sq = dx*dx + dy*dy + dz*dz + dw*dw;
    #pragma unroll
    for (int o = 16; o > 0; o >>= 1) sq += __shfl_xor_sync(0xffffffffu, sq, o);
    if ((t & 31) == 0) sred[t >> 5] = sq;
    __syncthreads();
    float tot2 = 0.f;
    #pragma unroll
    for (int i = 0; i < 8; i++) tot2 += sred[i];
    const float inv = rsqrtf(tot2 * (1.0f / DMODEL) + 1e-5f);

    float4 g = reinterpret_cast<const float4*>(gamma)[t];
    float4 be = reinterpret_cast<const float4*>(beta)[t];
    float4 o;
    o.x = dx * inv * g.x + be.x;
    o.y = dy * inv * g.y + be.y;
    o.z = dz * inv * g.z + be.z;
    o.w = dw * inv * g.w + be.w;
    reinterpret_cast<float4*>(out + row * DMODEL)[t] = o;
}

// ---------------------------------------------------------------------------
extern "C" void kernel_launch(void* const* d_in, const int* in_sizes, int n_in,
                              void* d_out, int out_size) {
    const float* q     = (const float*)d_in[0];
    const float* k     = (const float*)d_in[1];
    const float* v     = (const float*)d_in[2];
    const int*   mask  = (const int*)  d_in[3];
    const float* wq    = (const float*)d_in[4];
    const float* bq    = (const float*)d_in[5];
    const float* wk    = (const float*)d_in[6];
    const float* bk    = (const float*)d_in[7];
    const float* wv    = (const float*)d_in[8];
    const float* bv    = (const float*)d_in[9];
    const float* wo    = (const float*)d_in[10];
    const float* bo    = (const float*)d_in[11];
    const float* gamma = (const float*)d_in[12];
    const float* beta  = (const float*)d_in[13];

    float* out  = (float*)d_out;
    float* attn = out + ATT_OFF;

    void* sp = nullptr;
    cudaGetSymbolAddress(&sp, g_scratch);
    const size_t PS = (size_t)MROWS * DMODEL;
    float* gq      = (float*)sp;
    float* gk      = gq + PS;
    float* gv      = gk + PS;
    float* go      = gv + PS;
    float* pctx    = go + PS;            // SPLITK x PS
    float* partial = pctx + SPLITK * PS;

    cudaFuncSetAttribute(scores_exp,   cudaFuncAttributeMaxDynamicSharedMemorySize, SC_SMEM);
    cudaFuncSetAttribute(pv_norm,      cudaFuncAttributeMaxDynamicSharedMemorySize, PV_SMEM);
    cudaFuncSetAttribute(gemm_nt_tf32, cudaFuncAttributeMaxDynamicSharedMemorySize, VP_SMEM);

    dim3 gQK(DMODEL / 128, MROWS / 128, 2);             // (8, 32, 2)
    gemm_qk_bf16x3<<<gQK, 256>>>(q, k, wq, wk, bq, bk, gq, gk);

    dim3 gProj(DMODEL / 128, MROWS / 128);              // (8, 32)
    gemm_nt_tf32<<<gProj, 256, VP_SMEM>>>(v, wv, bv, gv);

    dim3 gScores(BATCH * NHEADS, NKT, SEQ / 128);       // (32, 16, 16) bh fastest
    scores_exp<<<gScores, 256, SC_SMEM>>>(gq, gk, mask, attn, partial);

    dim3 gPV(SPLITK, SEQ / 128, BATCH * NHEADS);        // (2, 16, 32)
    pv_norm<<<gPV, 256, PV_SMEM>>>(attn, gv, partial, pctx);

    gemm_o_tf32<<<gProj, 256>>>(pctx, wo, bo, go);

    ln_kernel<<<MROWS, 256>>>(q, go, gamma, beta, out);
}